// round 2
// baseline (speedup 1.0000x reference)
#include <cuda_runtime.h>
#include <math.h>

// ---------------- problem constants ----------------
#define NENT   100000
#define HDIM   128
#define NR2    460
#define TT     4
#define EE     200000
#define SLOPE  0.22916666666666666f   // (1/8 + 1/3)/2

#define MT     64      // rows per GEMM block
#define SWS    132     // sW row stride in floats (pad 4 to kill trans-store conflicts)
#define SMEMB  ((128*SWS + 64*128)*4) // 100352 bytes dynamic smem

// ---------------- scratch (device globals; no allocation allowed) ----------------
__device__ float g_hA [NENT*HDIM];
__device__ float g_hB [NENT*HDIM];
__device__ float g_cur[NENT*HDIM];
__device__ float g_HW [NENT*HDIM];
__device__ float g_agg[NENT*HDIM];
__device__ float g_nrm[NENT*HDIM];   // reused later as hn2
__device__ float g_hn1[NENT*HDIM];
__device__ float g_deg[NENT];
__device__ float g_relA[NR2*HDIM];
__device__ float g_relB[NR2*HDIM];
__device__ float g_R1 [NR2*HDIM];
__device__ float g_R2 [NR2*HDIM];

__device__ __forceinline__ float sigf(float x) { return 1.0f / (1.0f + __expf(-x)); }

// ---------------- h0 = l2norm(dynamic_emb) ----------------
__global__ void l2norm_kernel(const float* __restrict__ in, float* __restrict__ out, int M) {
    int w    = (blockIdx.x * blockDim.x + threadIdx.x) >> 5;
    int lane = threadIdx.x & 31;
    if (w >= M) return;
    float4 v = ((const float4*)in)[w*32 + lane];
    float ss = v.x*v.x + v.y*v.y + v.z*v.z + v.w*v.w;
    #pragma unroll
    for (int o = 16; o; o >>= 1) ss += __shfl_xor_sync(0xffffffffu, ss, o);
    float inv = 1.0f / fmaxf(sqrtf(ss), 1e-12f);
    v.x *= inv; v.y *= inv; v.z *= inv; v.w *= inv;
    ((float4*)out)[w*32 + lane] = v;
}

// ---------------- relation GRUCell: x=[emb_rel|rel] (2H) -> rel_new (H) ----------------
__global__ void gru_kernel(const float* __restrict__ emb_rel, const float* __restrict__ rel,
                           const float* __restrict__ Wx, const float* __restrict__ Wh,
                           const float* __restrict__ bx, const float* __restrict__ bh,
                           float* __restrict__ relOut) {
    __shared__ float s_x[8][256];   // [emb_rel | rel] rows
    int t = threadIdx.x;            // 0..127 (one output feature)
    int row0 = blockIdx.x * 8;
    for (int i = t; i < 8*64; i += 128) {
        int rr = i >> 6, c4 = i & 63;
        int m = row0 + rr;
        float4 v = make_float4(0.f,0.f,0.f,0.f);
        if (m < NR2)
            v = (c4 < 32) ? ((const float4*)emb_rel)[m*32 + c4]
                          : ((const float4*)rel)[m*32 + (c4-32)];
        *(float4*)&s_x[rr][c4*4] = v;
    }
    __syncthreads();
    const float4* wr = (const float4*)(Wx + (      t)*256);
    const float4* wz = (const float4*)(Wx + (128 + t)*256);
    const float4* wn = (const float4*)(Wx + (256 + t)*256);
    const float4* vr = (const float4*)(Wh + (      t)*128);
    const float4* vz = (const float4*)(Wh + (128 + t)*128);
    const float4* vn = (const float4*)(Wh + (256 + t)*128);
    float bxr = bx[t], bxz = bx[128+t], bxn = bx[256+t];
    float bhr = bh[t], bhz = bh[128+t], bhn = bh[256+t];
    for (int rr = 0; rr < 8; rr++) {
        int m = row0 + rr;
        if (m >= NR2) break;
        float gxr = bxr, gxz = bxz, gxn = bxn;
        float ghr = bhr, ghz = bhz, ghn = bhn;
        #pragma unroll 8
        for (int k4 = 0; k4 < 64; k4++) {
            float4 x = *(float4*)&s_x[rr][k4*4];
            float4 a = wr[k4], b = wz[k4], c = wn[k4];
            gxr += x.x*a.x + x.y*a.y + x.z*a.z + x.w*a.w;
            gxz += x.x*b.x + x.y*b.y + x.z*b.z + x.w*b.w;
            gxn += x.x*c.x + x.y*c.y + x.z*c.z + x.w*c.w;
        }
        #pragma unroll 8
        for (int k4 = 0; k4 < 32; k4++) {
            float4 x = *(float4*)&s_x[rr][128 + k4*4];
            float4 a = vr[k4], b = vz[k4], c = vn[k4];
            ghr += x.x*a.x + x.y*a.y + x.z*a.z + x.w*a.w;
            ghz += x.x*b.x + x.y*b.y + x.z*b.z + x.w*b.w;
            ghn += x.x*c.x + x.y*c.y + x.z*c.z + x.w*c.w;
        }
        float r  = sigf(gxr + ghr);
        float z  = sigf(gxz + ghz);
        float nn = tanhf(gxn + r*ghn);
        float hp = s_x[rr][128 + t];
        relOut[m*128 + t] = (1.0f - z)*nn + z*hp;
    }
}

// ---------------- edge gather + vector-atomic scatter ----------------
__global__ void edge_kernel(const int* __restrict__ src, const int* __restrict__ dst,
                            const int* __restrict__ ety, const float* __restrict__ HW,
                            const float* __restrict__ R, float* __restrict__ agg,
                            float* __restrict__ deg, int E, int do_deg) {
    int e    = (blockIdx.x * blockDim.x + threadIdx.x) >> 5;
    int lane = threadIdx.x & 31;
    if (e >= E) return;
    int s = __ldg(src + e), d = __ldg(dst + e), r = __ldg(ety + e);
    float4 v  = __ldg(((const float4*)HW) + s*32 + lane);
    float4 rv = __ldg(((const float4*)R)  + r*32 + lane);
    v.x += rv.x; v.y += rv.y; v.z += rv.z; v.w += rv.w;
    float* p = agg + (size_t)d*128 + lane*4;
    asm volatile("red.global.add.v4.f32 [%0], {%1,%2,%3,%4};"
                 :: "l"(p), "f"(v.x), "f"(v.y), "f"(v.z), "f"(v.w) : "memory");
    if (do_deg && lane == 0) atomicAdd(deg + d, 1.0f);
}

// ---------------- fused GEMM (+epilogue variants) ----------------
// C[M,128] = f( A[M,128] @ W[128,128] , extras ), W staged in smem, A tile in smem.
enum { M_PLAIN=0, M_FIN=1, M_FINNORM=2, M_TG=3, M_GATE=4, M_TDIFF=5 };

template<int MODE>
__global__ __launch_bounds__(256, 2) void gemm_kernel(
    const float* __restrict__ A, const float* __restrict__ W, float* __restrict__ C,
    int M,
    const float* __restrict__ agg, const float* __restrict__ deg,
    const float* __restrict__ bias, const float* __restrict__ Hprev)
{
    extern __shared__ float sm[];
    float* sW = sm;               // [128][SWS]
    float* sA = sm + 128*SWS;     // [64][128]
    int tid  = threadIdx.x;
    int w    = tid >> 5, lane = tid & 31;
    int row0 = blockIdx.x * MT;
    int c0   = lane * 4;

    float acc[8][4];
    #pragma unroll
    for (int r = 0; r < 8; r++)
        #pragma unroll
        for (int c = 0; c < 4; c++) acc[r][c] = 0.0f;

    const int nphase = (MODE == M_GATE) ? 2 : 1;
    for (int ph = 0; ph < nphase; ph++) {
        // --- stage W ---
        if (MODE == M_GATE) {            // Ws[k][n] = gate_W[n][ph*128 + k]  (x @ W^T)
            for (int i = tid; i < 128*128; i += 256) {
                int n = i >> 7, k = i & 127;
                sW[k*SWS + n] = W[n*256 + ph*128 + k];
            }
        } else if (MODE == M_TDIFF) {    // Ws[k][n] = tdW[n][k]
            for (int i = tid; i < 128*128; i += 256) {
                int n = i >> 7, k = i & 127;
                sW[k*SWS + n] = W[n*128 + k];
            }
        } else {                         // Ws[k][n] = W[k][n]
            for (int i = tid; i < 128*32; i += 256) {
                int k = i >> 5, c4 = i & 31;
                float4 v = ((const float4*)W)[i];
                *(float4*)&sW[k*SWS + c4*4] = v;
            }
        }
        // --- stage A tile ---
        const float* Asrc = (MODE == M_GATE && ph == 1) ? Hprev : A;
        for (int i = tid; i < 64*32; i += 256) {
            int lr = i >> 5, c4 = i & 31;
            int gr = row0 + lr;
            float4 v = make_float4(0.f,0.f,0.f,0.f);
            if (gr < M) {
                v = ((const float4*)Asrc)[gr*32 + c4];
                if (MODE == M_TDIFF) {
                    float4 hv = ((const float4*)Hprev)[gr*32 + c4];
                    v.x -= hv.x; v.y -= hv.y; v.z -= hv.z; v.w -= hv.w;
                }
            }
            *(float4*)&sA[lr*128 + c4*4] = v;
        }
        __syncthreads();
        // --- compute ---
        #pragma unroll 4
        for (int kk = 0; kk < 128; kk += 4) {
            float4 w0 = *(float4*)&sW[(kk+0)*SWS + c0];
            float4 w1 = *(float4*)&sW[(kk+1)*SWS + c0];
            float4 w2 = *(float4*)&sW[(kk+2)*SWS + c0];
            float4 w3 = *(float4*)&sW[(kk+3)*SWS + c0];
            #pragma unroll
            for (int r = 0; r < 8; r++) {
                float4 a = *(float4*)&sA[(w*8 + r)*128 + kk];
                acc[r][0] += a.x*w0.x + a.y*w1.x + a.z*w2.x + a.w*w3.x;
                acc[r][1] += a.x*w0.y + a.y*w1.y + a.z*w2.y + a.w*w3.y;
                acc[r][2] += a.x*w0.z + a.y*w1.z + a.z*w2.z + a.w*w3.z;
                acc[r][3] += a.x*w0.w + a.y*w1.w + a.z*w2.w + a.w*w3.w;
            }
        }
        if (MODE == M_GATE && ph == 0) __syncthreads();
    }

    // --- epilogue ---
    #pragma unroll
    for (int r = 0; r < 8; r++) {
        int lr = w*8 + r;
        int gr = row0 + lr;
        if (gr >= M) break;                 // uniform across the warp
        float4 v = make_float4(acc[r][0], acc[r][1], acc[r][2], acc[r][3]);

        if (MODE == M_FIN || MODE == M_FINNORM) {
            float inv = 1.0f / fmaxf(__ldg(deg + gr), 1.0f);
            float4 ag = __ldg(((const float4*)agg) + gr*32 + lane);
            v.x = fmaf(ag.x, inv, v.x); v.y = fmaf(ag.y, inv, v.y);
            v.z = fmaf(ag.z, inv, v.z); v.w = fmaf(ag.w, inv, v.w);
            v.x = v.x >= 0.f ? v.x : SLOPE*v.x;  v.y = v.y >= 0.f ? v.y : SLOPE*v.y;
            v.z = v.z >= 0.f ? v.z : SLOPE*v.z;  v.w = v.w >= 0.f ? v.w : SLOPE*v.w;
            if (MODE == M_FINNORM) {
                float ss = v.x*v.x + v.y*v.y + v.z*v.z + v.w*v.w;
                #pragma unroll
                for (int o = 16; o; o >>= 1) ss += __shfl_xor_sync(0xffffffffu, ss, o);
                float s = 1.0f / fmaxf(sqrtf(ss), 1e-12f);
                v.x *= s; v.y *= s; v.z *= s; v.w *= s;
            }
        } else if (MODE == M_TG) {
            float4 b = __ldg(((const float4*)bias) + lane);
            float4 g = make_float4(sigf(v.x+b.x), sigf(v.y+b.y), sigf(v.z+b.z), sigf(v.w+b.w));
            float4 a = *(float4*)&sA[lr*128 + c0];                 // nrm (A tile)
            float4 h = __ldg(((const float4*)Hprev) + gr*32 + lane);
            v.x = g.x*a.x + (1.f-g.x)*h.x;  v.y = g.y*a.y + (1.f-g.y)*h.y;
            v.z = g.z*a.z + (1.f-g.z)*h.z;  v.w = g.w*a.w + (1.f-g.w)*h.w;
        } else if (MODE == M_GATE) {
            float4 b = __ldg(((const float4*)bias) + lane);
            float4 g = make_float4(sigf(v.x+b.x), sigf(v.y+b.y), sigf(v.z+b.z), sigf(v.w+b.w));
            float4 h = *(float4*)&sA[lr*128 + c0];                 // phase-1 A tile = Hprev
            float4 a = __ldg(((const float4*)A) + gr*32 + lane);   // hn1
            v.x = g.x*a.x + (1.f-g.x)*h.x;  v.y = g.y*a.y + (1.f-g.y)*h.y;
            v.z = g.z*a.z + (1.f-g.z)*h.z;  v.w = g.w*a.w + (1.f-g.w)*h.w;
        } else if (MODE == M_TDIFF) {
            float4 b = __ldg(((const float4*)bias) + lane);
            float4 y = make_float4(fmaxf(v.x+b.x, 0.f), fmaxf(v.y+b.y, 0.f),
                                   fmaxf(v.z+b.z, 0.f), fmaxf(v.w+b.w, 0.f));
            float4 a = __ldg(((const float4*)A) + gr*32 + lane);   // hn2
            v.x = a.x + y.x; v.y = a.y + y.y; v.z = a.z + y.z; v.w = a.w + y.w;
        }
        ((float4*)C)[gr*32 + lane] = v;
    }
}

// ---------------- host driver ----------------
extern "C" void kernel_launch(void* const* d_in, const int* in_sizes, int n_in,
                              void* d_out, int out_size) {
    const int*   src     = (const int*)d_in[0];
    const int*   dst     = (const int*)d_in[1];
    const int*   ety     = (const int*)d_in[2];
    const float* dyn     = (const float*)d_in[3];
    const float* emb_rel = (const float*)d_in[4];
    const float* Wn1     = (const float*)d_in[5];
    const float* Wl1     = (const float*)d_in[6];
    const float* Wn2     = (const float*)d_in[7];
    const float* Wl2     = (const float*)d_in[8];
    const float* gWx     = (const float*)d_in[9];
    const float* gWh     = (const float*)d_in[10];
    const float* gbx     = (const float*)d_in[11];
    const float* gbh     = (const float*)d_in[12];
    const float* gateW   = (const float*)d_in[13];
    const float* gateb   = (const float*)d_in[14];
    const float* tdW     = (const float*)d_in[15];
    const float* tdb     = (const float*)d_in[16];
    const float* tgW     = (const float*)d_in[17];
    const float* tgb     = (const float*)d_in[18];
    float* out = (float*)d_out;

    float *hA,*hB,*cur,*HW,*agg,*nrm,*hn1,*deg,*relA,*relB,*R1,*R2;
    cudaGetSymbolAddress((void**)&hA,  g_hA);
    cudaGetSymbolAddress((void**)&hB,  g_hB);
    cudaGetSymbolAddress((void**)&cur, g_cur);
    cudaGetSymbolAddress((void**)&HW,  g_HW);
    cudaGetSymbolAddress((void**)&agg, g_agg);
    cudaGetSymbolAddress((void**)&nrm, g_nrm);
    cudaGetSymbolAddress((void**)&hn1, g_hn1);
    cudaGetSymbolAddress((void**)&deg, g_deg);
    cudaGetSymbolAddress((void**)&relA,g_relA);
    cudaGetSymbolAddress((void**)&relB,g_relB);
    cudaGetSymbolAddress((void**)&R1,  g_R1);
    cudaGetSymbolAddress((void**)&R2,  g_R2);

    cudaFuncSetAttribute((const void*)gemm_kernel<M_PLAIN>,  cudaFuncAttributeMaxDynamicSharedMemorySize, SMEMB);
    cudaFuncSetAttribute((const void*)gemm_kernel<M_FIN>,    cudaFuncAttributeMaxDynamicSharedMemorySize, SMEMB);
    cudaFuncSetAttribute((const void*)gemm_kernel<M_FINNORM>,cudaFuncAttributeMaxDynamicSharedMemorySize, SMEMB);
    cudaFuncSetAttribute((const void*)gemm_kernel<M_TG>,     cudaFuncAttributeMaxDynamicSharedMemorySize, SMEMB);
    cudaFuncSetAttribute((const void*)gemm_kernel<M_GATE>,   cudaFuncAttributeMaxDynamicSharedMemorySize, SMEMB);
    cudaFuncSetAttribute((const void*)gemm_kernel<M_TDIFF>,  cudaFuncAttributeMaxDynamicSharedMemorySize, SMEMB);

    const int GB = (NENT + MT - 1) / MT;   // 1563
    const int RB = (NR2  + MT - 1) / MT;   // 8
    const int EB = (EE*32 + 255) / 256;    // edge blocks

    // h0 = l2norm(dynamic_emb)
    l2norm_kernel<<<(NENT + 7)/8, 256>>>(dyn, hA, NENT);

    const float* relPrev = emb_rel;
    float* relBufs[2] = { relB, relA };
    float* h     = hA;
    float* hnext = hB;

    for (int t = 0; t < TT; t++) {
        const int* sT = src + t*EE;
        const int* dT = dst + t*EE;
        const int* eT = ety + t*EE;
        float* relNext = relBufs[t & 1];

        cudaMemsetAsync(agg, 0, (size_t)NENT*HDIM*sizeof(float));
        cudaMemsetAsync(deg, 0, (size_t)NENT*sizeof(float));

        gru_kernel<<<(NR2 + 7)/8, 128>>>(emb_rel, relPrev, gWx, gWh, gbx, gbh, relNext);
        gemm_kernel<M_PLAIN><<<RB, 256, SMEMB>>>(relNext, Wn1, R1, NR2, 0,0,0,0);
        gemm_kernel<M_PLAIN><<<RB, 256, SMEMB>>>(relNext, Wn2, R2, NR2, 0,0,0,0);

        // layer 1
        gemm_kernel<M_PLAIN><<<GB, 256, SMEMB>>>(h, Wn1, HW, NENT, 0,0,0,0);
        edge_kernel<<<EB, 256>>>(sT, dT, eT, HW, R1, agg, deg, EE, 1);
        gemm_kernel<M_FIN><<<GB, 256, SMEMB>>>(h, Wl1, cur, NENT, agg, deg, 0, 0);

        // layer 2
        cudaMemsetAsync(agg, 0, (size_t)NENT*HDIM*sizeof(float));
        gemm_kernel<M_PLAIN><<<GB, 256, SMEMB>>>(cur, Wn2, HW, NENT, 0,0,0,0);
        edge_kernel<<<EB, 256>>>(sT, dT, eT, HW, R2, agg, deg, EE, 0);
        gemm_kernel<M_FINNORM><<<GB, 256, SMEMB>>>(cur, Wl2, nrm, NENT, agg, deg, 0, 0);

        // time gate -> hn1 ; gated fusion -> nrm (reused as hn2) ; tdiff -> next h
        gemm_kernel<M_TG><<<GB, 256, SMEMB>>>(nrm, tgW, hn1, NENT, 0,0, tgb, h);
        gemm_kernel<M_GATE><<<GB, 256, SMEMB>>>(hn1, gateW, nrm, NENT, 0,0, gateb, h);
        float* target = (t == TT-1) ? out : hnext;
        gemm_kernel<M_TDIFF><<<GB, 256, SMEMB>>>(nrm, tdW, target, NENT, 0,0, tdb, h);

        relPrev = relNext;
        if (t < TT-1) { float* tmp = h; h = hnext; hnext = tmp; }
    }
}

// round 4
// speedup vs baseline: 1.1285x; 1.1285x over previous
#include <cuda_runtime.h>
#include <cuda_bf16.h>
#include <cstdint>
#include <math.h>

// ---------------- problem constants ----------------
#define NENT   100000
#define HDIM   128
#define NR2    460
#define TT     4
#define EE     200000
#define SLOPE  0.22916666666666666f

// ---------------- smem layout ----------------
#define SM_BIAS  0
#define SM_NORM  512
#define SM_AHI   1024
#define SM_ALO   (SM_AHI + 32768)
#define SM_WHI   (SM_ALO + 32768)
#define SM_WLO   (SM_WHI + 32768)
#define SM_EPI   (SM_WLO + 32768)
#define ES       129
#define SMEMB    (SM_EPI + 128*ES*4)   // 198144 bytes

enum { M_PLAIN=0, M_FIN=1, M_FINNORM=2, M_TG=3, M_GATE=4, M_TDIFF=5 };

// ---------------- scratch ----------------
__device__ float g_hA [NENT*HDIM];
__device__ float g_hB [NENT*HDIM];
__device__ float g_cur[NENT*HDIM];
__device__ float g_HW [NENT*HDIM];
__device__ float g_agg[NENT*HDIM];
__device__ float g_nrm[NENT*HDIM];
__device__ float g_hn1[NENT*HDIM];
__device__ float g_deg[NENT];
__device__ float g_relA[NR2*HDIM];
__device__ float g_relB[NR2*HDIM];
__device__ float g_R1 [NR2*HDIM];
__device__ float g_R2 [NR2*HDIM];
__device__ unsigned char g_Wpack[8][65536];   // [matrix][hi 32KB | lo 32KB], swizzled

__device__ __forceinline__ float sigf(float x) { return 1.0f / (1.0f + __expf(-x)); }

__device__ __forceinline__ uint32_t smem_u32(const void* p) {
    uint32_t a;
    asm("{ .reg .u64 t; cvta.to.shared.u64 t, %1; cvt.u32.u64 %0, t; }" : "=r"(a) : "l"(p));
    return a;
}
// 256B-row swizzle: XOR 16B-chunk select bits [6:4] with row bits [10:8]
__device__ __host__ __forceinline__ uint32_t swz(uint32_t off) {
    return off ^ ((off >> 4) & 0x70);
}
__device__ __forceinline__ void ldsm4(uint32_t* r, uint32_t a) {
    asm volatile("ldmatrix.sync.aligned.m8n8.x4.shared.b16 {%0,%1,%2,%3}, [%4];"
                 : "=r"(r[0]),"=r"(r[1]),"=r"(r[2]),"=r"(r[3]) : "r"(a));
}
__device__ __forceinline__ void ldsm4t(uint32_t* r, uint32_t a) {
    asm volatile("ldmatrix.sync.aligned.m8n8.x4.trans.shared.b16 {%0,%1,%2,%3}, [%4];"
                 : "=r"(r[0]),"=r"(r[1]),"=r"(r[2]),"=r"(r[3]) : "r"(a));
}
__device__ __forceinline__ void mma16816(float* d, const uint32_t* a, uint32_t b0, uint32_t b1) {
    asm volatile("mma.sync.aligned.m16n8k16.row.col.f32.bf16.bf16.f32 "
                 "{%0,%1,%2,%3},{%4,%5,%6,%7},{%8,%9},{%0,%1,%2,%3};"
                 : "+f"(d[0]),"+f"(d[1]),"+f"(d[2]),"+f"(d[3])
                 : "r"(a[0]),"r"(a[1]),"r"(a[2]),"r"(a[3]),"r"(b0),"r"(b1));
}

// ---------------- weight pack: mma-ready swizzled hi/lo images ----------------
__global__ void pack_kernel(const float* __restrict__ Wn1, const float* __restrict__ Wl1,
                            const float* __restrict__ Wn2, const float* __restrict__ Wl2,
                            const float* __restrict__ tgW, const float* __restrict__ gateW,
                            const float* __restrict__ tdW) {
    int m = blockIdx.x;
    const float* W; int mode;
    switch (m) {
        case 0: W = Wn1;  mode = 0; break;
        case 1: W = Wl1;  mode = 0; break;
        case 2: W = Wn2;  mode = 0; break;
        case 3: W = Wl2;  mode = 0; break;
        case 4: W = tgW;  mode = 0; break;
        case 5: W = gateW; mode = 2; break;
        case 6: W = gateW; mode = 3; break;
        default: W = tdW; mode = 1; break;
    }
    unsigned char* base = g_Wpack[m];
    for (int idx = threadIdx.x; idx < 16384; idx += blockDim.x) {
        int k = idx >> 7, n = idx & 127;
        float v;
        if      (mode == 0) v = W[k * 128 + n];
        else if (mode == 1) v = W[n * 128 + k];
        else if (mode == 2) v = W[n * 256 + k];
        else                v = W[n * 256 + 128 + k];
        __nv_bfloat16 hi = __float2bfloat16(v);
        __nv_bfloat16 lo = __float2bfloat16(v - __bfloat162float(hi));
        uint32_t o = swz((uint32_t)(k * 256 + n * 2));
        *(__nv_bfloat16*)(base + o)         = hi;
        *(__nv_bfloat16*)(base + 32768 + o) = lo;
    }
}

// ---------------- l2norm ----------------
__global__ void l2norm_kernel(const float* __restrict__ in, float* __restrict__ out, int M) {
    int w = (blockIdx.x * blockDim.x + threadIdx.x) >> 5;
    int lane = threadIdx.x & 31;
    if (w >= M) return;
    float4 v = ((const float4*)in)[w*32 + lane];
    float ss = v.x*v.x + v.y*v.y + v.z*v.z + v.w*v.w;
    #pragma unroll
    for (int o = 16; o; o >>= 1) ss += __shfl_xor_sync(0xffffffffu, ss, o);
    float inv = 1.0f / fmaxf(sqrtf(ss), 1e-12f);
    v.x *= inv; v.y *= inv; v.z *= inv; v.w *= inv;
    ((float4*)out)[w*32 + lane] = v;
}

// ---------------- relation GRUCell ----------------
__global__ void gru_kernel(const float* __restrict__ emb_rel, const float* __restrict__ rel,
                           const float* __restrict__ Wx, const float* __restrict__ Wh,
                           const float* __restrict__ bx, const float* __restrict__ bh,
                           float* __restrict__ relOut) {
    __shared__ float s_x[8][256];
    int t = threadIdx.x;
    int row0 = blockIdx.x * 8;
    for (int i = t; i < 8*64; i += 128) {
        int rr = i >> 6, c4 = i & 63;
        int m = row0 + rr;
        float4 v = make_float4(0.f,0.f,0.f,0.f);
        if (m < NR2)
            v = (c4 < 32) ? ((const float4*)emb_rel)[m*32 + c4]
                          : ((const float4*)rel)[m*32 + (c4-32)];
        *(float4*)&s_x[rr][c4*4] = v;
    }
    __syncthreads();
    const float4* wr = (const float4*)(Wx + (      t)*256);
    const float4* wz = (const float4*)(Wx + (128 + t)*256);
    const float4* wn = (const float4*)(Wx + (256 + t)*256);
    const float4* vr = (const float4*)(Wh + (      t)*128);
    const float4* vz = (const float4*)(Wh + (128 + t)*128);
    const float4* vn = (const float4*)(Wh + (256 + t)*128);
    float bxr = bx[t], bxz = bx[128+t], bxn = bx[256+t];
    float bhr = bh[t], bhz = bh[128+t], bhn = bh[256+t];
    for (int rr = 0; rr < 8; rr++) {
        int m = row0 + rr;
        if (m >= NR2) break;
        float gxr = bxr, gxz = bxz, gxn = bxn;
        float ghr = bhr, ghz = bhz, ghn = bhn;
        #pragma unroll 8
        for (int k4 = 0; k4 < 64; k4++) {
            float4 x = *(float4*)&s_x[rr][k4*4];
            float4 a = wr[k4], b = wz[k4], c = wn[k4];
            gxr += x.x*a.x + x.y*a.y + x.z*a.z + x.w*a.w;
            gxz += x.x*b.x + x.y*b.y + x.z*b.z + x.w*b.w;
            gxn += x.x*c.x + x.y*c.y + x.z*c.z + x.w*c.w;
        }
        #pragma unroll 8
        for (int k4 = 0; k4 < 32; k4++) {
            float4 x = *(float4*)&s_x[rr][128 + k4*4];
            float4 a = vr[k4], b = vz[k4], c = vn[k4];
            ghr += x.x*a.x + x.y*a.y + x.z*a.z + x.w*a.w;
            ghz += x.x*b.x + x.y*b.y + x.z*b.z + x.w*b.w;
            ghn += x.x*c.x + x.y*c.y + x.z*c.z + x.w*c.w;
        }
        float r  = sigf(gxr + ghr);
        float z  = sigf(gxz + ghz);
        float nn = tanhf(gxn + r*ghn);
        float hp = s_x[rr][128 + t];
        relOut[m*128 + t] = (1.0f - z)*nn + z*hp;
    }
}

// ---------------- edge gather + vector-atomic scatter ----------------
__global__ void edge_kernel(const int* __restrict__ src, const int* __restrict__ dst,
                            const int* __restrict__ ety, const float* __restrict__ HW,
                            const float* __restrict__ R, float* __restrict__ agg,
                            float* __restrict__ deg, int E, int do_deg) {
    int e = (blockIdx.x * blockDim.x + threadIdx.x) >> 5;
    int lane = threadIdx.x & 31;
    if (e >= E) return;
    int s = __ldg(src + e), d = __ldg(dst + e), r = __ldg(ety + e);
    float4 v  = __ldg(((const float4*)HW) + s*32 + lane);
    float4 rv = __ldg(((const float4*)R)  + r*32 + lane);
    v.x += rv.x; v.y += rv.y; v.z += rv.z; v.w += rv.w;
    float* p = agg + (size_t)d*128 + lane*4;
    asm volatile("red.global.add.v4.f32 [%0], {%1,%2,%3,%4};"
                 :: "l"(p), "f"(v.x), "f"(v.y), "f"(v.z), "f"(v.w) : "memory");
    if (do_deg && lane == 0) atomicAdd(deg + d, 1.0f);
}

// ---------------- staging helpers ----------------
__device__ __forceinline__ void stage_A(char* smc, const float* A, const float* Hsub,
                                        int row0, int M, int tid) {
    for (int i = tid; i < 2048; i += 256) {
        int r = i >> 4, c8 = i & 15;          // 8 floats per chunk pair
        int gr = row0 + r;
        float4 v0 = make_float4(0.f,0.f,0.f,0.f), v1 = v0;
        if (gr < M) {
            v0 = __ldg(((const float4*)A) + (size_t)gr*32 + c8*2);
            v1 = __ldg(((const float4*)A) + (size_t)gr*32 + c8*2 + 1);
            if (Hsub) {
                float4 h0 = __ldg(((const float4*)Hsub) + (size_t)gr*32 + c8*2);
                float4 h1 = __ldg(((const float4*)Hsub) + (size_t)gr*32 + c8*2 + 1);
                v0.x -= h0.x; v0.y -= h0.y; v0.z -= h0.z; v0.w -= h0.w;
                v1.x -= h1.x; v1.y -= h1.y; v1.z -= h1.z; v1.w -= h1.w;
            }
        }
        float f[8] = {v0.x, v0.y, v0.z, v0.w, v1.x, v1.y, v1.z, v1.w};
        __nv_bfloat162 hi[4], lo[4];
        #pragma unroll
        for (int q = 0; q < 4; q++) {
            __nv_bfloat16 hx = __float2bfloat16(f[2*q]);
            __nv_bfloat16 hy = __float2bfloat16(f[2*q+1]);
            hi[q].x = hx; hi[q].y = hy;
            lo[q].x = __float2bfloat16(f[2*q]   - __bfloat162float(hx));
            lo[q].y = __float2bfloat16(f[2*q+1] - __bfloat162float(hy));
        }
        uint32_t off = swz((uint32_t)(r*256 + c8*16));
        *(uint4*)(smc + SM_AHI + off) = *(uint4*)hi;
        *(uint4*)(smc + SM_ALO + off) = *(uint4*)lo;
    }
}
__device__ __forceinline__ void stage_W(char* smc, const unsigned char* Wimg, int tid) {
    const float4* s = (const float4*)Wimg;   // 64KB hi|lo, already swizzled
    float4* d = (float4*)(smc + SM_WHI);
    for (int i = tid; i < 4096; i += 256) d[i] = s[i];
}

// ---------------- mma mainloop ----------------
__device__ __forceinline__ void mma_mainloop(uint32_t sb, int lid, int wm, int wn,
                                             float acc[2][8][4]) {
    #pragma unroll 1
    for (int k0 = 0; k0 < 128; k0 += 16) {
        uint32_t aH[2][4], aL[2][4];
        #pragma unroll
        for (int mi = 0; mi < 2; mi++) {
            int row = wm*32 + mi*16 + (lid & 15);
            int col = k0 + ((lid >> 4) << 3);
            uint32_t off = swz((uint32_t)(row*256 + col*2));
            ldsm4(aH[mi], sb + SM_AHI + off);
            ldsm4(aL[mi], sb + SM_ALO + off);
        }
        #pragma unroll
        for (int p = 0; p < 4; p++) {
            int krow = k0 + (lid & 15);
            int col  = wn*64 + p*16 + ((lid >> 4) << 3);
            uint32_t off = swz((uint32_t)(krow*256 + col*2));
            uint32_t bH[4], bL[4];
            ldsm4t(bH, sb + SM_WHI + off);
            ldsm4t(bL, sb + SM_WLO + off);
            #pragma unroll
            for (int mi = 0; mi < 2; mi++) {
                mma16816(acc[mi][2*p],   aH[mi], bH[0], bH[1]);
                mma16816(acc[mi][2*p],   aL[mi], bH[0], bH[1]);
                mma16816(acc[mi][2*p],   aH[mi], bL[0], bL[1]);
                mma16816(acc[mi][2*p+1], aH[mi], bH[2], bH[3]);
                mma16816(acc[mi][2*p+1], aL[mi], bH[2], bH[3]);
                mma16816(acc[mi][2*p+1], aH[mi], bL[2], bL[3]);
            }
        }
    }
}

// ---------------- mma GEMM + fused epilogues ----------------
template<int MODE>
__global__ __launch_bounds__(256, 1) void mmagemm(
    const float* __restrict__ A, const unsigned char* __restrict__ Wimg,
    float* __restrict__ C, int M,
    const float* __restrict__ agg, const float* __restrict__ deg,
    const float* __restrict__ bias, const float* __restrict__ Hprev,
    const float* __restrict__ A2, const unsigned char* __restrict__ W2img)
{
    extern __shared__ char smc[];
    uint32_t sb = smem_u32(smc);
    int tid = threadIdx.x, wid = tid >> 5, lid = tid & 31;
    int wm = wid & 3, wn = wid >> 2;
    int row0 = blockIdx.x * 128;

    if (MODE >= M_TG && tid < 128) ((float*)(smc + SM_BIAS))[tid] = __ldg(bias + tid);

    stage_A(smc, A, (MODE == M_TDIFF) ? Hprev : (const float*)0, row0, M, tid);
    stage_W(smc, Wimg, tid);
    __syncthreads();

    float acc[2][8][4];
    #pragma unroll
    for (int a = 0; a < 2; a++)
        #pragma unroll
        for (int b = 0; b < 8; b++)
            #pragma unroll
            for (int c = 0; c < 4; c++) acc[a][b][c] = 0.0f;

    mma_mainloop(sb, lid, wm, wn, acc);

    if (MODE == M_GATE) {
        __syncthreads();
        stage_A(smc, A2, (const float*)0, row0, M, tid);
        stage_W(smc, W2img, tid);
        __syncthreads();
        mma_mainloop(sb, lid, wm, wn, acc);
    }

    // ---- accum -> transposed epi smem [col][row] ----
    float* epi = (float*)(smc + SM_EPI);
    #pragma unroll
    for (int mi = 0; mi < 2; mi++)
        #pragma unroll
        for (int nj = 0; nj < 8; nj++) {
            int r = wm*32 + mi*16 + (lid >> 2);
            int c = wn*64 + nj*8 + (lid & 3)*2;
            epi[c*ES + r]         = acc[mi][nj][0];
            epi[(c+1)*ES + r]     = acc[mi][nj][1];
            epi[c*ES + r + 8]     = acc[mi][nj][2];
            epi[(c+1)*ES + r + 8] = acc[mi][nj][3];
        }
    __syncthreads();

    // ---- pass 1: per-row mode math (2 threads per row, 64 cols each) ----
    float* snorm = (float*)(smc + SM_NORM);
    const float* sbias = (const float*)(smc + SM_BIAS);
    if (MODE != M_PLAIN) {
        int r = tid >> 1, half = tid & 1;
        int gr = row0 + r;
        bool rv = (gr < M);
        float invdeg = 1.0f;
        if ((MODE == M_FIN || MODE == M_FINNORM) && rv)
            invdeg = 1.0f / fmaxf(__ldg(deg + gr), 1.0f);
        const float* X = (MODE == M_FIN || MODE == M_FINNORM) ? agg
                       : (MODE == M_GATE) ? A : Hprev;
        float ss = 0.0f;
        for (int j4 = 0; j4 < 16; j4++) {
            int c = half*64 + j4*4;
            float4 aux = make_float4(0.f,0.f,0.f,0.f);
            if (rv) aux = __ldg(((const float4*)X) + (size_t)gr*32 + (c >> 2));
            float auxv[4] = {aux.x, aux.y, aux.z, aux.w};
            float av[4];
            if (MODE >= M_TG) {
                uint32_t o0 = swz((uint32_t)(r*256 + c*2));
                uint32_t o1 = swz((uint32_t)(r*256 + (c+2)*2));
                __nv_bfloat162 h0 = *(__nv_bfloat162*)(smc + SM_AHI + o0);
                __nv_bfloat162 l0 = *(__nv_bfloat162*)(smc + SM_ALO + o0);
                __nv_bfloat162 h1 = *(__nv_bfloat162*)(smc + SM_AHI + o1);
                __nv_bfloat162 l1 = *(__nv_bfloat162*)(smc + SM_ALO + o1);
                av[0] = __bfloat162float(h0.x) + __bfloat162float(l0.x);
                av[1] = __bfloat162float(h0.y) + __bfloat162float(l0.y);
                av[2] = __bfloat162float(h1.x) + __bfloat162float(l1.x);
                av[3] = __bfloat162float(h1.y) + __bfloat162float(l1.y);
            }
            #pragma unroll
            for (int q = 0; q < 4; q++) {
                float v = epi[(size_t)(c+q)*ES + r];
                float o;
                if (MODE == M_FIN || MODE == M_FINNORM) {
                    o = fmaf(auxv[q], invdeg, v);
                    o = o >= 0.f ? o : SLOPE * o;
                    if (MODE == M_FINNORM) ss += o*o;
                } else if (MODE == M_TG) {          // av=cur(norm), aux=h
                    float g = sigf(v + sbias[c+q]);
                    o = g*av[q] + (1.f-g)*auxv[q];
                } else if (MODE == M_GATE) {        // av=h (phase2 smem), aux=hn1
                    float g = sigf(v + sbias[c+q]);
                    o = g*auxv[q] + (1.f-g)*av[q];
                } else {                            // TDIFF: av=(hn2-h), aux=h
                    float y = fmaxf(v + sbias[c+q], 0.f);
                    o = (av[q] + auxv[q]) + y;
                }
                epi[(size_t)(c+q)*ES + r] = o;
            }
        }
        if (MODE == M_FINNORM) {
            ss += __shfl_xor_sync(0xffffffffu, ss, 1);
            if (half == 0) snorm[r] = 1.0f / fmaxf(sqrtf(ss), 1e-12f);
        }
    }
    __syncthreads();

    // ---- pass 2: coalesced writeout (thread = column) ----
    int c = tid & 127;
    int rb = (tid >> 7) * 64;
    for (int r = rb; r < rb + 64; r++) {
        int gro = row0 + r;
        if (gro >= M) break;
        float v = epi[(size_t)c*ES + r];
        if (MODE == M_FINNORM) v *= snorm[r];
        C[(size_t)gro*128 + c] = v;
    }
}

// ---------------- host driver ----------------
extern "C" void kernel_launch(void* const* d_in, const int* in_sizes, int n_in,
                              void* d_out, int out_size) {
    const int*   src     = (const int*)d_in[0];
    const int*   dst     = (const int*)d_in[1];
    const int*   ety     = (const int*)d_in[2];
    const float* dyn     = (const float*)d_in[3];
    const float* emb_rel = (const float*)d_in[4];
    const float* Wn1     = (const float*)d_in[5];
    const float* Wl1     = (const float*)d_in[6];
    const float* Wn2     = (const float*)d_in[7];
    const float* Wl2     = (const float*)d_in[8];
    const float* gWx     = (const float*)d_in[9];
    const float* gWh     = (const float*)d_in[10];
    const float* gbx     = (const float*)d_in[11];
    const float* gbh     = (const float*)d_in[12];
    const float* gateW   = (const float*)d_in[13];
    const float* gateb   = (const float*)d_in[14];
    const float* tdW     = (const float*)d_in[15];
    const float* tdb     = (const float*)d_in[16];
    const float* tgW     = (const float*)d_in[17];
    const float* tgb     = (const float*)d_in[18];
    float* out = (float*)d_out;

    float *hA,*hB,*cur,*HW,*agg,*nrm,*hn1,*deg;
    float *relA,*relB,*R1,*R2;
    unsigned char* Wp;
    cudaGetSymbolAddress((void**)&hA,  g_hA);
    cudaGetSymbolAddress((void**)&hB,  g_hB);
    cudaGetSymbolAddress((void**)&cur, g_cur);
    cudaGetSymbolAddress((void**)&HW,  g_HW);
    cudaGetSymbolAddress((void**)&agg, g_agg);
    cudaGetSymbolAddress((void**)&nrm, g_nrm);
    cudaGetSymbolAddress((void**)&hn1, g_hn1);
    cudaGetSymbolAddress((void**)&deg, g_deg);
    cudaGetSymbolAddress((void**)&relA,g_relA);
    cudaGetSymbolAddress((void**)&relB,g_relB);
    cudaGetSymbolAddress((void**)&R1,  g_R1);
    cudaGetSymbolAddress((void**)&R2,  g_R2);
    cudaGetSymbolAddress((void**)&Wp,  g_Wpack);

    cudaFuncSetAttribute((const void*)mmagemm<M_PLAIN>,   cudaFuncAttributeMaxDynamicSharedMemorySize, SMEMB);
    cudaFuncSetAttribute((const void*)mmagemm<M_FIN>,     cudaFuncAttributeMaxDynamicSharedMemorySize, SMEMB);
    cudaFuncSetAttribute((const void*)mmagemm<M_FINNORM>, cudaFuncAttributeMaxDynamicSharedMemorySize, SMEMB);
    cudaFuncSetAttribute((const void*)mmagemm<M_TG>,      cudaFuncAttributeMaxDynamicSharedMemorySize, SMEMB);
    cudaFuncSetAttribute((const void*)mmagemm<M_GATE>,    cudaFuncAttributeMaxDynamicSharedMemorySize, SMEMB);
    cudaFuncSetAttribute((const void*)mmagemm<M_TDIFF>,   cudaFuncAttributeMaxDynamicSharedMemorySize, SMEMB);

    const unsigned char* pWn1 = Wp + 0*65536;
    const unsigned char* pWl1 = Wp + 1*65536;
    const unsigned char* pWn2 = Wp + 2*65536;
    const unsigned char* pWl2 = Wp + 3*65536;
    const unsigned char* pTg  = Wp + 4*65536;
    const unsigned char* pGa  = Wp + 5*65536;
    const unsigned char* pGb  = Wp + 6*65536;
    const unsigned char* pTd  = Wp + 7*65536;

    const int GB = (NENT + 127) / 128;   // 782
    const int RB = (NR2  + 127) / 128;   // 4
    const int EB = (EE*32 + 255) / 256;

    pack_kernel<<<8, 256>>>(Wn1, Wl1, Wn2, Wl2, tgW, gateW, tdW);
    l2norm_kernel<<<(NENT + 7)/8, 256>>>(dyn, hA, NENT);

    const float* relPrev = emb_rel;
    float* relBufs[2] = { relB, relA };
    float* h     = hA;
    float* hnext = hB;

    for (int t = 0; t < TT; t++) {
        const int* sT = src + t*EE;
        const int* dT = dst + t*EE;
        const int* eT = ety + t*EE;
        float* relNext = relBufs[t & 1];

        cudaMemsetAsync(agg, 0, (size_t)NENT*HDIM*sizeof(float));
        cudaMemsetAsync(deg, 0, (size_t)NENT*sizeof(float));

        gru_kernel<<<(NR2 + 7)/8, 128>>>(emb_rel, relPrev, gWx, gWh, gbx, gbh, relNext);
        mmagemm<M_PLAIN><<<RB, 256, SMEMB>>>(relNext, pWn1, R1, NR2, 0,0,0,0,0,0);
        mmagemm<M_PLAIN><<<RB, 256, SMEMB>>>(relNext, pWn2, R2, NR2, 0,0,0,0,0,0);

        // layer 1
        mmagemm<M_PLAIN><<<GB, 256, SMEMB>>>(h, pWn1, HW, NENT, 0,0,0,0,0,0);
        edge_kernel<<<EB, 256>>>(sT, dT, eT, HW, R1, agg, deg, EE, 1);
        mmagemm<M_FIN><<<GB, 256, SMEMB>>>(h, pWl1, cur, NENT, agg, deg, 0,0,0,0);

        // layer 2
        cudaMemsetAsync(agg, 0, (size_t)NENT*HDIM*sizeof(float));
        mmagemm<M_PLAIN><<<GB, 256, SMEMB>>>(cur, pWn2, HW, NENT, 0,0,0,0,0,0);
        edge_kernel<<<EB, 256>>>(sT, dT, eT, HW, R2, agg, deg, EE, 0);
        mmagemm<M_FINNORM><<<GB, 256, SMEMB>>>(cur, pWl2, nrm, NENT, agg, deg, 0,0,0,0);

        // time gate -> hn1 ; gated fusion -> nrm (as hn2) ; tdiff -> next h
        mmagemm<M_TG><<<GB, 256, SMEMB>>>(nrm, pTg, hn1, NENT, 0,0, tgb, h, 0,0);
        mmagemm<M_GATE><<<GB, 256, SMEMB>>>(hn1, pGa, nrm, NENT, 0,0, gateb, 0, h, pGb);
        float* target = (t == TT-1) ? out : hnext;
        mmagemm<M_TDIFF><<<GB, 256, SMEMB>>>(nrm, pTd, target, NENT, 0,0, tdb, h, 0,0);

        relPrev = relNext;
        if (t < TT-1) { float* tmp = h; h = hnext; hnext = tmp; }
    }
}

// round 5
// speedup vs baseline: 1.5587x; 1.3812x over previous
#include <cuda_runtime.h>
#include <cuda_bf16.h>
#include <cstdint>
#include <math.h>

// ---------------- problem constants ----------------
#define NENT   100000
#define HDIM   128
#define NR2    460
#define TT     4
#define EE     200000
#define SLOPE  0.22916666666666666f

enum { M_PLAIN=0, M_FIN=1, M_FINNORM=2 };

// ---- mmagemm smem layout ----
#define GM_SRED  0                     // 256 f32 (FINNORM row partials)
#define GM_A     2048                  // hi 32KB | lo 32KB
#define GM_W     (GM_A + 65536)
#define GM_SIZE  (GM_W + 65536)        // 133120

// ---- tail smem layout ----
#define TL_BIAS  0                     // tg @0, gate @512, td @1024
#define TL_A1    2048
#define TL_A2    (TL_A1 + 65536)
#define TL_W     (TL_A2 + 65536)
#define TL_SIZE  (TL_W + 65536)        // 198656

// ---------------- scratch ----------------
__device__ float g_hA [NENT*HDIM];
__device__ float g_hB [NENT*HDIM];
__device__ float g_cur[NENT*HDIM];
__device__ float g_HW [NENT*HDIM];
__device__ float g_agg[NENT*HDIM];
__device__ float g_nrm[NENT*HDIM];
__device__ float g_deg[NENT];
__device__ float g_relA[NR2*HDIM];
__device__ float g_relB[NR2*HDIM];
__device__ float g_R1 [NR2*HDIM];
__device__ float g_R2 [NR2*HDIM];
__device__ unsigned char g_Wpack[8][65536];   // [matrix][hi 32KB | lo 32KB], swizzled

__device__ __forceinline__ float sigf(float x) { return 1.0f / (1.0f + __expf(-x)); }

__device__ __forceinline__ uint32_t smem_u32(const void* p) {
    uint32_t a;
    asm("{ .reg .u64 t; cvta.to.shared.u64 t, %1; cvt.u32.u64 %0, t; }" : "=r"(a) : "l"(p));
    return a;
}
__device__ __host__ __forceinline__ uint32_t swz(uint32_t off) {
    return off ^ ((off >> 4) & 0x70);
}
__device__ __forceinline__ void ldsm4(uint32_t* r, uint32_t a) {
    asm volatile("ldmatrix.sync.aligned.m8n8.x4.shared.b16 {%0,%1,%2,%3}, [%4];"
                 : "=r"(r[0]),"=r"(r[1]),"=r"(r[2]),"=r"(r[3]) : "r"(a));
}
__device__ __forceinline__ void ldsm4t(uint32_t* r, uint32_t a) {
    asm volatile("ldmatrix.sync.aligned.m8n8.x4.trans.shared.b16 {%0,%1,%2,%3}, [%4];"
                 : "=r"(r[0]),"=r"(r[1]),"=r"(r[2]),"=r"(r[3]) : "r"(a));
}
__device__ __forceinline__ void mma16816(float* d, const uint32_t* a, uint32_t b0, uint32_t b1) {
    asm volatile("mma.sync.aligned.m16n8k16.row.col.f32.bf16.bf16.f32 "
                 "{%0,%1,%2,%3},{%4,%5,%6,%7},{%8,%9},{%0,%1,%2,%3};"
                 : "+f"(d[0]),"+f"(d[1]),"+f"(d[2]),"+f"(d[3])
                 : "r"(a[0]),"r"(a[1]),"r"(a[2]),"r"(a[3]),"r"(b0),"r"(b1));
}

// ---------------- weight pack ----------------
__global__ void pack_kernel(const float* __restrict__ Wn1, const float* __restrict__ Wl1,
                            const float* __restrict__ Wn2, const float* __restrict__ Wl2,
                            const float* __restrict__ tgW, const float* __restrict__ gateW,
                            const float* __restrict__ tdW) {
    int m = blockIdx.x;
    const float* W; int mode;
    switch (m) {
        case 0: W = Wn1;  mode = 0; break;
        case 1: W = Wl1;  mode = 0; break;
        case 2: W = Wn2;  mode = 0; break;
        case 3: W = Wl2;  mode = 0; break;
        case 4: W = tgW;  mode = 0; break;
        case 5: W = gateW; mode = 2; break;
        case 6: W = gateW; mode = 3; break;
        default: W = tdW; mode = 1; break;
    }
    unsigned char* base = g_Wpack[m];
    for (int idx = threadIdx.x; idx < 16384; idx += blockDim.x) {
        int k = idx >> 7, n = idx & 127;
        float v;
        if      (mode == 0) v = W[k * 128 + n];
        else if (mode == 1) v = W[n * 128 + k];
        else if (mode == 2) v = W[n * 256 + k];
        else                v = W[n * 256 + 128 + k];
        __nv_bfloat16 hi = __float2bfloat16(v);
        __nv_bfloat16 lo = __float2bfloat16(v - __bfloat162float(hi));
        uint32_t o = swz((uint32_t)(k * 256 + n * 2));
        *(__nv_bfloat16*)(base + o)         = hi;
        *(__nv_bfloat16*)(base + 32768 + o) = lo;
    }
}

// ---------------- l2norm ----------------
__global__ void l2norm_kernel(const float* __restrict__ in, float* __restrict__ out, int M) {
    int w = (blockIdx.x * blockDim.x + threadIdx.x) >> 5;
    int lane = threadIdx.x & 31;
    if (w >= M) return;
    float4 v = ((const float4*)in)[w*32 + lane];
    float ss = v.x*v.x + v.y*v.y + v.z*v.z + v.w*v.w;
    #pragma unroll
    for (int o = 16; o; o >>= 1) ss += __shfl_xor_sync(0xffffffffu, ss, o);
    float inv = 1.0f / fmaxf(sqrtf(ss), 1e-12f);
    v.x *= inv; v.y *= inv; v.z *= inv; v.w *= inv;
    ((float4*)out)[w*32 + lane] = v;
}

// ---------------- relation GRUCell ----------------
__global__ void gru_kernel(const float* __restrict__ emb_rel, const float* __restrict__ rel,
                           const float* __restrict__ Wx, const float* __restrict__ Wh,
                           const float* __restrict__ bx, const float* __restrict__ bh,
                           float* __restrict__ relOut) {
    __shared__ float s_x[8][256];
    int t = threadIdx.x;
    int row0 = blockIdx.x * 8;
    for (int i = t; i < 8*64; i += 128) {
        int rr = i >> 6, c4 = i & 63;
        int m = row0 + rr;
        float4 v = make_float4(0.f,0.f,0.f,0.f);
        if (m < NR2)
            v = (c4 < 32) ? ((const float4*)emb_rel)[m*32 + c4]
                          : ((const float4*)rel)[m*32 + (c4-32)];
        *(float4*)&s_x[rr][c4*4] = v;
    }
    __syncthreads();
    const float4* wr = (const float4*)(Wx + (      t)*256);
    const float4* wz = (const float4*)(Wx + (128 + t)*256);
    const float4* wn = (const float4*)(Wx + (256 + t)*256);
    const float4* vr = (const float4*)(Wh + (      t)*128);
    const float4* vz = (const float4*)(Wh + (128 + t)*128);
    const float4* vn = (const float4*)(Wh + (256 + t)*128);
    float bxr = bx[t], bxz = bx[128+t], bxn = bx[256+t];
    float bhr = bh[t], bhz = bh[128+t], bhn = bh[256+t];
    for (int rr = 0; rr < 8; rr++) {
        int m = row0 + rr;
        if (m >= NR2) break;
        float gxr = bxr, gxz = bxz, gxn = bxn;
        float ghr = bhr, ghz = bhz, ghn = bhn;
        #pragma unroll 8
        for (int k4 = 0; k4 < 64; k4++) {
            float4 x = *(float4*)&s_x[rr][k4*4];
            float4 a = wr[k4], b = wz[k4], c = wn[k4];
            gxr += x.x*a.x + x.y*a.y + x.z*a.z + x.w*a.w;
            gxz += x.x*b.x + x.y*b.y + x.z*b.z + x.w*b.w;
            gxn += x.x*c.x + x.y*c.y + x.z*c.z + x.w*c.w;
        }
        #pragma unroll 8
        for (int k4 = 0; k4 < 32; k4++) {
            float4 x = *(float4*)&s_x[rr][128 + k4*4];
            float4 a = vr[k4], b = vz[k4], c = vn[k4];
            ghr += x.x*a.x + x.y*a.y + x.z*a.z + x.w*a.w;
            ghz += x.x*b.x + x.y*b.y + x.z*b.z + x.w*b.w;
            ghn += x.x*c.x + x.y*c.y + x.z*c.z + x.w*c.w;
        }
        float r  = sigf(gxr + ghr);
        float z  = sigf(gxz + ghz);
        float nn = tanhf(gxn + r*ghn);
        float hp = s_x[rr][128 + t];
        relOut[m*128 + t] = (1.0f - z)*nn + z*hp;
    }
}

// ---------------- edge gather + vector-atomic scatter ----------------
__global__ void edge_kernel(const int* __restrict__ src, const int* __restrict__ dst,
                            const int* __restrict__ ety, const float* __restrict__ HW,
                            const float* __restrict__ R, float* __restrict__ agg,
                            float* __restrict__ deg, int E, int do_deg) {
    int e = (blockIdx.x * blockDim.x + threadIdx.x) >> 5;
    int lane = threadIdx.x & 31;
    if (e >= E) return;
    int s = __ldg(src + e), d = __ldg(dst + e), r = __ldg(ety + e);
    float4 v  = __ldg(((const float4*)HW) + s*32 + lane);
    float4 rv = __ldg(((const float4*)R)  + r*32 + lane);
    v.x += rv.x; v.y += rv.y; v.z += rv.z; v.w += rv.w;
    float* p = agg + (size_t)d*128 + lane*4;
    asm volatile("red.global.add.v4.f32 [%0], {%1,%2,%3,%4};"
                 :: "l"(p), "f"(v.x), "f"(v.y), "f"(v.z), "f"(v.w) : "memory");
    if (do_deg && lane == 0) atomicAdd(deg + d, 1.0f);
}

// ---------------- staging ----------------
__device__ __forceinline__ void stage_A_g(char* smc, int dstOff, const float* A,
                                          int row0, int M, int tid) {
    for (int i = tid; i < 2048; i += 256) {
        int r = i >> 4, c8 = i & 15;
        int gr = row0 + r;
        float4 v0 = make_float4(0.f,0.f,0.f,0.f), v1 = v0;
        if (gr < M) {
            v0 = __ldg(((const float4*)A) + (size_t)gr*32 + c8*2);
            v1 = __ldg(((const float4*)A) + (size_t)gr*32 + c8*2 + 1);
        }
        float f[8] = {v0.x, v0.y, v0.z, v0.w, v1.x, v1.y, v1.z, v1.w};
        __nv_bfloat162 hi[4], lo[4];
        #pragma unroll
        for (int q = 0; q < 4; q++) {
            __nv_bfloat16 hx = __float2bfloat16(f[2*q]);
            __nv_bfloat16 hy = __float2bfloat16(f[2*q+1]);
            hi[q].x = hx; hi[q].y = hy;
            lo[q].x = __float2bfloat16(f[2*q]   - __bfloat162float(hx));
            lo[q].y = __float2bfloat16(f[2*q+1] - __bfloat162float(hy));
        }
        uint32_t off = swz((uint32_t)(r*256 + c8*16));
        *(uint4*)(smc + dstOff + off)         = *(uint4*)hi;
        *(uint4*)(smc + dstOff + 32768 + off) = *(uint4*)lo;
    }
}
__device__ __forceinline__ void stage_W_s(char* smc, int dstOff, const unsigned char* Wimg, int tid) {
    const float4* s = (const float4*)Wimg;
    float4* d = (float4*)(smc + dstOff);
    #pragma unroll 4
    for (int i = tid; i < 4096; i += 256) d[i] = s[i];
}
// read reconstructed fp32 pair from a staged hi/lo A buffer at (row, col..col+1)
__device__ __forceinline__ float2 readA2(const char* smc, int off, int row, int c) {
    uint32_t o = swz((uint32_t)(row*256 + c*2));
    __nv_bfloat162 h = *(const __nv_bfloat162*)(smc + off + o);
    __nv_bfloat162 l = *(const __nv_bfloat162*)(smc + off + 32768 + o);
    return make_float2(__bfloat162float(h.x) + __bfloat162float(l.x),
                       __bfloat162float(h.y) + __bfloat162float(l.y));
}
// stage fragment-resident values (optionally minus reconstruction of subOff buffer)
__device__ __forceinline__ void stage_A_r(char* smc, int dstOff, const float hv[2][8][4],
                                          int lid, int wm, int wn, int subOff) {
    #pragma unroll
    for (int mi = 0; mi < 2; mi++)
        #pragma unroll
        for (int rr = 0; rr < 2; rr++) {
            int row = wm*32 + mi*16 + rr*8 + (lid >> 2);
            #pragma unroll
            for (int nj = 0; nj < 8; nj++) {
                int c = wn*64 + nj*8 + (lid & 3)*2;
                float v0 = hv[mi][nj][rr*2], v1 = hv[mi][nj][rr*2+1];
                if (subOff >= 0) {
                    float2 s = readA2(smc, subOff, row, c);
                    v0 -= s.x; v1 -= s.y;
                }
                __nv_bfloat16 h0 = __float2bfloat16(v0), h1 = __float2bfloat16(v1);
                __nv_bfloat162 hi2, lo2;
                hi2.x = h0; hi2.y = h1;
                lo2.x = __float2bfloat16(v0 - __bfloat162float(h0));
                lo2.y = __float2bfloat16(v1 - __bfloat162float(h1));
                uint32_t o = swz((uint32_t)(row*256 + c*2));
                *(__nv_bfloat162*)(smc + dstOff + o)         = hi2;
                *(__nv_bfloat162*)(smc + dstOff + 32768 + o) = lo2;
            }
        }
}

// ---------------- mainloop: acc += A(aOff) @ W(wOff), split-bf16 3 products ----------------
__device__ __forceinline__ void gemm_tile(uint32_t sb, uint32_t aOff, uint32_t wOff,
                                          int lid, int wm, int wn, float acc[2][8][4]) {
    #pragma unroll
    for (int k0 = 0; k0 < 128; k0 += 16) {
        uint32_t aH[2][4], aL[2][4];
        #pragma unroll
        for (int mi = 0; mi < 2; mi++) {
            int row = wm*32 + mi*16 + (lid & 15);
            int col = k0 + ((lid >> 4) << 3);
            uint32_t off = swz((uint32_t)(row*256 + col*2));
            ldsm4(aH[mi], sb + aOff + off);
            ldsm4(aL[mi], sb + aOff + 32768 + off);
        }
        #pragma unroll
        for (int p = 0; p < 4; p++) {
            int krow = k0 + (lid & 15);
            int col  = wn*64 + p*16 + ((lid >> 4) << 3);
            uint32_t off = swz((uint32_t)(krow*256 + col*2));
            uint32_t bH[4], bL[4];
            ldsm4t(bH, sb + wOff + off);
            ldsm4t(bL, sb + wOff + 32768 + off);
            #pragma unroll
            for (int mi = 0; mi < 2; mi++) {
                mma16816(acc[mi][2*p],   aH[mi], bH[0], bH[1]);
                mma16816(acc[mi][2*p],   aL[mi], bH[0], bH[1]);
                mma16816(acc[mi][2*p],   aH[mi], bL[0], bL[1]);
                mma16816(acc[mi][2*p+1], aH[mi], bH[2], bH[3]);
                mma16816(acc[mi][2*p+1], aL[mi], bH[2], bH[3]);
                mma16816(acc[mi][2*p+1], aH[mi], bL[2], bL[3]);
            }
        }
    }
}
#define ZERO_ACC(acc) { _Pragma("unroll") for (int a_=0;a_<2;a_++) _Pragma("unroll") for (int b_=0;b_<8;b_++) _Pragma("unroll") for (int c_=0;c_<4;c_++) acc[a_][b_][c_]=0.0f; }

// ---------------- GEMM + fragment epilogue ----------------
template<int MODE>
__global__ __launch_bounds__(256, 1) void mmagemm(
    const float* __restrict__ A, const unsigned char* __restrict__ Wimg,
    float* __restrict__ C, int M,
    const float* __restrict__ agg, const float* __restrict__ deg)
{
    extern __shared__ char smc[];
    uint32_t sb = smem_u32(smc);
    int tid = threadIdx.x, wid = tid >> 5, lid = tid & 31;
    int wm = wid & 3, wn = wid >> 2;
    int row0 = blockIdx.x * 128;

    stage_A_g(smc, GM_A, A, row0, M, tid);
    stage_W_s(smc, GM_W, Wimg, tid);
    __syncthreads();

    float acc[2][8][4];
    ZERO_ACC(acc);
    gemm_tile(sb, GM_A, GM_W, lid, wm, wn, acc);

    float* sred = (float*)(smc + GM_SRED);

    if (MODE == M_PLAIN) {
        #pragma unroll
        for (int mi = 0; mi < 2; mi++)
            #pragma unroll
            for (int rr = 0; rr < 2; rr++) {
                int gr = row0 + wm*32 + mi*16 + rr*8 + (lid >> 2);
                if (gr >= M) continue;
                #pragma unroll
                for (int nj = 0; nj < 8; nj++) {
                    int c = wn*64 + nj*8 + (lid & 3)*2;
                    *(float2*)(C + (size_t)gr*128 + c) =
                        make_float2(acc[mi][nj][rr*2], acc[mi][nj][rr*2+1]);
                }
            }
    } else {
        // leaky(agg/deg + acc), optional row l2norm
        #pragma unroll
        for (int mi = 0; mi < 2; mi++)
            #pragma unroll
            for (int rr = 0; rr < 2; rr++) {
                int lr = wm*32 + mi*16 + rr*8 + (lid >> 2);
                int gr = row0 + lr;
                bool rv = (gr < M);
                float invdeg = rv ? 1.0f / fmaxf(__ldg(deg + gr), 1.0f) : 1.0f;
                float ss = 0.0f;
                #pragma unroll
                for (int nj = 0; nj < 8; nj++) {
                    int c = wn*64 + nj*8 + (lid & 3)*2;
                    float2 ag = rv ? *(const float2*)(agg + (size_t)gr*128 + c)
                                   : make_float2(0.f, 0.f);
                    float o0 = fmaf(ag.x, invdeg, acc[mi][nj][rr*2]);
                    float o1 = fmaf(ag.y, invdeg, acc[mi][nj][rr*2+1]);
                    o0 = o0 >= 0.f ? o0 : SLOPE*o0;
                    o1 = o1 >= 0.f ? o1 : SLOPE*o1;
                    acc[mi][nj][rr*2]   = o0;
                    acc[mi][nj][rr*2+1] = o1;
                    if (MODE == M_FINNORM) ss += o0*o0 + o1*o1;
                }
                if (MODE == M_FINNORM) {
                    ss += __shfl_xor_sync(0xffffffffu, ss, 1);
                    ss += __shfl_xor_sync(0xffffffffu, ss, 2);
                    if ((lid & 3) == 0) sred[wn*128 + lr] = ss;
                }
            }
        if (MODE == M_FINNORM) __syncthreads();
        #pragma unroll
        for (int mi = 0; mi < 2; mi++)
            #pragma unroll
            for (int rr = 0; rr < 2; rr++) {
                int lr = wm*32 + mi*16 + rr*8 + (lid >> 2);
                int gr = row0 + lr;
                if (gr >= M) continue;
                float inv = 1.0f;
                if (MODE == M_FINNORM) {
                    float tot = sred[lr] + sred[128 + lr];
                    inv = 1.0f / fmaxf(sqrtf(tot), 1e-12f);
                }
                #pragma unroll
                for (int nj = 0; nj < 8; nj++) {
                    int c = wn*64 + nj*8 + (lid & 3)*2;
                    *(float2*)(C + (size_t)gr*128 + c) =
                        make_float2(acc[mi][nj][rr*2]*inv, acc[mi][nj][rr*2+1]*inv);
                }
            }
    }
}

// ---------------- fused tail: time-gate + gated fusion + tdiff (4 GEMM units) ----------------
__global__ __launch_bounds__(256, 1) void tail_kernel(
    const float* __restrict__ nrm, const float* __restrict__ h,
    const unsigned char* __restrict__ pTg, const unsigned char* __restrict__ pGa,
    const unsigned char* __restrict__ pGb, const unsigned char* __restrict__ pTd,
    const float* __restrict__ tgb, const float* __restrict__ gateb,
    const float* __restrict__ tdb, float* __restrict__ C, int M)
{
    extern __shared__ char smc[];
    uint32_t sb = smem_u32(smc);
    int tid = threadIdx.x, wid = tid >> 5, lid = tid & 31;
    int wm = wid & 3, wn = wid >> 2;
    int row0 = blockIdx.x * 128;

    if (tid < 128) {
        ((float*)(smc + TL_BIAS))[tid]       = __ldg(tgb + tid);
        ((float*)(smc + TL_BIAS + 512))[tid] = __ldg(gateb + tid);
        ((float*)(smc + TL_BIAS + 1024))[tid]= __ldg(tdb + tid);
    }
    stage_A_g(smc, TL_A1, nrm, row0, M, tid);
    stage_A_g(smc, TL_A2, h,   row0, M, tid);
    stage_W_s(smc, TL_W, pTg, tid);
    __syncthreads();

    const float* btg = (const float*)(smc + TL_BIAS);
    const float* bga = (const float*)(smc + TL_BIAS + 512);
    const float* btd = (const float*)(smc + TL_BIAS + 1024);

    float acc[2][8][4];
    float hv[2][8][4];   // carries hn1, then hn2

    // ---- phase 1: time gate ----
    ZERO_ACC(acc);
    gemm_tile(sb, TL_A1, TL_W, lid, wm, wn, acc);
    #pragma unroll
    for (int mi = 0; mi < 2; mi++)
        #pragma unroll
        for (int rr = 0; rr < 2; rr++) {
            int row = wm*32 + mi*16 + rr*8 + (lid >> 2);
            #pragma unroll
            for (int nj = 0; nj < 8; nj++) {
                int c = wn*64 + nj*8 + (lid & 3)*2;
                float2 nv = readA2(smc, TL_A1, row, c);
                float2 hh = readA2(smc, TL_A2, row, c);
                float g0 = sigf(acc[mi][nj][rr*2]   + btg[c]);
                float g1 = sigf(acc[mi][nj][rr*2+1] + btg[c+1]);
                hv[mi][nj][rr*2]   = g0*nv.x + (1.f-g0)*hh.x;
                hv[mi][nj][rr*2+1] = g1*nv.y + (1.f-g1)*hh.y;
            }
        }
    __syncthreads();

    // ---- phase 2: gated fusion (hn1@Ga + h@Gb) ----
    stage_A_r(smc, TL_A1, hv, lid, wm, wn, -1);
    stage_W_s(smc, TL_W, pGa, tid);
    __syncthreads();
    ZERO_ACC(acc);
    gemm_tile(sb, TL_A1, TL_W, lid, wm, wn, acc);
    __syncthreads();
    stage_W_s(smc, TL_W, pGb, tid);
    __syncthreads();
    gemm_tile(sb, TL_A2, TL_W, lid, wm, wn, acc);
    #pragma unroll
    for (int mi = 0; mi < 2; mi++)
        #pragma unroll
        for (int rr = 0; rr < 2; rr++) {
            int row = wm*32 + mi*16 + rr*8 + (lid >> 2);
            #pragma unroll
            for (int nj = 0; nj < 8; nj++) {
                int c = wn*64 + nj*8 + (lid & 3)*2;
                float2 hh = readA2(smc, TL_A2, row, c);
                float g0 = sigf(acc[mi][nj][rr*2]   + bga[c]);
                float g1 = sigf(acc[mi][nj][rr*2+1] + bga[c+1]);
                hv[mi][nj][rr*2]   = g0*hv[mi][nj][rr*2]   + (1.f-g0)*hh.x;
                hv[mi][nj][rr*2+1] = g1*hv[mi][nj][rr*2+1] + (1.f-g1)*hh.y;
            }
        }
    __syncthreads();

    // ---- phase 3: temporal difference fusion ----
    stage_A_r(smc, TL_A1, hv, lid, wm, wn, TL_A2);   // stage (hn2 - h)
    stage_W_s(smc, TL_W, pTd, tid);
    __syncthreads();
    ZERO_ACC(acc);
    gemm_tile(sb, TL_A1, TL_W, lid, wm, wn, acc);
    #pragma unroll
    for (int mi = 0; mi < 2; mi++)
        #pragma unroll
        for (int rr = 0; rr < 2; rr++) {
            int gr = row0 + wm*32 + mi*16 + rr*8 + (lid >> 2);
            if (gr >= M) continue;
            #pragma unroll
            for (int nj = 0; nj < 8; nj++) {
                int c = wn*64 + nj*8 + (lid & 3)*2;
                float y0 = fmaxf(acc[mi][nj][rr*2]   + btd[c],   0.f);
                float y1 = fmaxf(acc[mi][nj][rr*2+1] + btd[c+1], 0.f);
                *(float2*)(C + (size_t)gr*128 + c) =
                    make_float2(hv[mi][nj][rr*2] + y0, hv[mi][nj][rr*2+1] + y1);
            }
        }
}

// ---------------- host driver ----------------
extern "C" void kernel_launch(void* const* d_in, const int* in_sizes, int n_in,
                              void* d_out, int out_size) {
    const int*   src     = (const int*)d_in[0];
    const int*   dst     = (const int*)d_in[1];
    const int*   ety     = (const int*)d_in[2];
    const float* dyn     = (const float*)d_in[3];
    const float* emb_rel = (const float*)d_in[4];
    const float* Wn1     = (const float*)d_in[5];
    const float* Wl1     = (const float*)d_in[6];
    const float* Wn2     = (const float*)d_in[7];
    const float* Wl2     = (const float*)d_in[8];
    const float* gWx     = (const float*)d_in[9];
    const float* gWh     = (const float*)d_in[10];
    const float* gbx     = (const float*)d_in[11];
    const float* gbh     = (const float*)d_in[12];
    const float* gateW   = (const float*)d_in[13];
    const float* gateb   = (const float*)d_in[14];
    const float* tdW     = (const float*)d_in[15];
    const float* tdb     = (const float*)d_in[16];
    const float* tgW     = (const float*)d_in[17];
    const float* tgb     = (const float*)d_in[18];
    float* out = (float*)d_out;

    float *hA,*hB,*cur,*HW,*agg,*nrm,*deg,*relA,*relB,*R1,*R2;
    unsigned char* Wp;
    cudaGetSymbolAddress((void**)&hA,  g_hA);
    cudaGetSymbolAddress((void**)&hB,  g_hB);
    cudaGetSymbolAddress((void**)&cur, g_cur);
    cudaGetSymbolAddress((void**)&HW,  g_HW);
    cudaGetSymbolAddress((void**)&agg, g_agg);
    cudaGetSymbolAddress((void**)&nrm, g_nrm);
    cudaGetSymbolAddress((void**)&deg, g_deg);
    cudaGetSymbolAddress((void**)&relA,g_relA);
    cudaGetSymbolAddress((void**)&relB,g_relB);
    cudaGetSymbolAddress((void**)&R1,  g_R1);
    cudaGetSymbolAddress((void**)&R2,  g_R2);
    cudaGetSymbolAddress((void**)&Wp,  g_Wpack);

    cudaFuncSetAttribute((const void*)mmagemm<M_PLAIN>,   cudaFuncAttributeMaxDynamicSharedMemorySize, GM_SIZE);
    cudaFuncSetAttribute((const void*)mmagemm<M_FIN>,     cudaFuncAttributeMaxDynamicSharedMemorySize, GM_SIZE);
    cudaFuncSetAttribute((const void*)mmagemm<M_FINNORM>, cudaFuncAttributeMaxDynamicSharedMemorySize, GM_SIZE);
    cudaFuncSetAttribute((const void*)tail_kernel,        cudaFuncAttributeMaxDynamicSharedMemorySize, TL_SIZE);

    const unsigned char* pWn1 = Wp + 0*65536;
    const unsigned char* pWl1 = Wp + 1*65536;
    const unsigned char* pWn2 = Wp + 2*65536;
    const unsigned char* pWl2 = Wp + 3*65536;
    const unsigned char* pTg  = Wp + 4*65536;
    const unsigned char* pGa  = Wp + 5*65536;
    const unsigned char* pGb  = Wp + 6*65536;
    const unsigned char* pTd  = Wp + 7*65536;

    const int GB = (NENT + 127) / 128;   // 782
    const int RB = (NR2  + 127) / 128;   // 4
    const int EB = (EE*32 + 255) / 256;

    pack_kernel<<<8, 256>>>(Wn1, Wl1, Wn2, Wl2, tgW, gateW, tdW);
    l2norm_kernel<<<(NENT + 7)/8, 256>>>(dyn, hA, NENT);

    const float* relPrev = emb_rel;
    float* relBufs[2] = { relB, relA };
    float* h     = hA;
    float* hnext = hB;

    for (int t = 0; t < TT; t++) {
        const int* sT = src + t*EE;
        const int* dT = dst + t*EE;
        const int* eT = ety + t*EE;
        float* relNext = relBufs[t & 1];

        cudaMemsetAsync(agg, 0, (size_t)NENT*HDIM*sizeof(float));
        cudaMemsetAsync(deg, 0, (size_t)NENT*sizeof(float));

        gru_kernel<<<(NR2 + 7)/8, 128>>>(emb_rel, relPrev, gWx, gWh, gbx, gbh, relNext);
        mmagemm<M_PLAIN><<<RB, 256, GM_SIZE>>>(relNext, pWn1, R1, NR2, 0, 0);
        mmagemm<M_PLAIN><<<RB, 256, GM_SIZE>>>(relNext, pWn2, R2, NR2, 0, 0);

        // layer 1
        mmagemm<M_PLAIN><<<GB, 256, GM_SIZE>>>(h, pWn1, HW, NENT, 0, 0);
        edge_kernel<<<EB, 256>>>(sT, dT, eT, HW, R1, agg, deg, EE, 1);
        mmagemm<M_FIN><<<GB, 256, GM_SIZE>>>(h, pWl1, cur, NENT, agg, deg);

        // layer 2
        cudaMemsetAsync(agg, 0, (size_t)NENT*HDIM*sizeof(float));
        mmagemm<M_PLAIN><<<GB, 256, GM_SIZE>>>(cur, pWn2, HW, NENT, 0, 0);
        edge_kernel<<<EB, 256>>>(sT, dT, eT, HW, R2, agg, deg, EE, 0);
        mmagemm<M_FINNORM><<<GB, 256, GM_SIZE>>>(cur, pWl2, nrm, NENT, agg, deg);

        // fused tail: time gate + gated fusion + tdiff
        float* target = (t == TT-1) ? out : hnext;
        tail_kernel<<<GB, 256, TL_SIZE>>>(nrm, h, pTg, pGa, pGb, pTd,
                                          tgb, gateb, tdb, target, NENT);

        relPrev = relNext;
        if (t < TT-1) { float* tmp = h; h = hnext; hnext = tmp; }
    }
}

// round 6
// speedup vs baseline: 2.1354x; 1.3700x over previous
#include <cuda_runtime.h>
#include <cuda_bf16.h>
#include <cstdint>
#include <math.h>

// ---------------- problem constants ----------------
#define NENT   100000
#define HDIM   128
#define NR2    460
#define TT     4
#define EE     200000
#define SLOPE  0.22916666666666666f
#define NTHR   512

// ---- smem layouts ----
// plain / K2:
#define PG_A     2048
#define PG_W     (PG_A + 65536)
#define PG_SIZE  (PG_W + 65536)          // 133120
// K3:
#define K3_BTG   0
#define K3_BGA   512
#define K3_BTD   1024
#define K3_SRED  1536                    // 256 f32
#define K3_A1    4096
#define K3_A2    (K3_A1 + 65536)
#define K3_W     (K3_A2 + 65536)
#define K3_SIZE  (K3_W + 65536)          // 200704

// ---------------- scratch ----------------
__device__ float g_hA [NENT*HDIM];
__device__ float g_hB [NENT*HDIM];
__device__ float g_cur[NENT*HDIM];
__device__ float g_HW [NENT*HDIM];
__device__ float g_agg[NENT*HDIM];
__device__ float g_deg[NENT];
__device__ float g_relA[NR2*HDIM];
__device__ float g_relB[NR2*HDIM];
__device__ float g_R1 [NR2*HDIM];
__device__ float g_R2 [NR2*HDIM];
__device__ unsigned char g_Wpack[8][65536];   // [matrix][hi 32KB | lo 32KB], swizzled

__device__ __forceinline__ float sigf(float x) { return 1.0f / (1.0f + __expf(-x)); }

__device__ __forceinline__ uint32_t smem_u32(const void* p) {
    uint32_t a;
    asm("{ .reg .u64 t; cvta.to.shared.u64 t, %1; cvt.u32.u64 %0, t; }" : "=r"(a) : "l"(p));
    return a;
}
__device__ __host__ __forceinline__ uint32_t swz(uint32_t off) {
    return off ^ ((off >> 4) & 0x70);
}
__device__ __forceinline__ void ldsm4(uint32_t* r, uint32_t a) {
    asm volatile("ldmatrix.sync.aligned.m8n8.x4.shared.b16 {%0,%1,%2,%3}, [%4];"
                 : "=r"(r[0]),"=r"(r[1]),"=r"(r[2]),"=r"(r[3]) : "r"(a));
}
__device__ __forceinline__ void ldsm4t(uint32_t* r, uint32_t a) {
    asm volatile("ldmatrix.sync.aligned.m8n8.x4.trans.shared.b16 {%0,%1,%2,%3}, [%4];"
                 : "=r"(r[0]),"=r"(r[1]),"=r"(r[2]),"=r"(r[3]) : "r"(a));
}
__device__ __forceinline__ void mma16816(float* d, const uint32_t* a, uint32_t b0, uint32_t b1) {
    asm volatile("mma.sync.aligned.m16n8k16.row.col.f32.bf16.bf16.f32 "
                 "{%0,%1,%2,%3},{%4,%5,%6,%7},{%8,%9},{%0,%1,%2,%3};"
                 : "+f"(d[0]),"+f"(d[1]),"+f"(d[2]),"+f"(d[3])
                 : "r"(a[0]),"r"(a[1]),"r"(a[2]),"r"(a[3]),"r"(b0),"r"(b1));
}
__device__ __forceinline__ void cp16(uint32_t saddr, const void* gaddr) {
    asm volatile("cp.async.cg.shared.global [%0], [%1], 16;" :: "r"(saddr), "l"(gaddr));
}
__device__ __forceinline__ void cp_commit_wait() {
    asm volatile("cp.async.commit_group;");
    asm volatile("cp.async.wait_group 0;");
}

// ---------------- weight pack ----------------
__global__ void pack_kernel(const float* __restrict__ Wn1, const float* __restrict__ Wl1,
                            const float* __restrict__ Wn2, const float* __restrict__ Wl2,
                            const float* __restrict__ tgW, const float* __restrict__ gateW,
                            const float* __restrict__ tdW) {
    int m = blockIdx.x;
    const float* W; int mode;
    switch (m) {
        case 0: W = Wn1;  mode = 0; break;
        case 1: W = Wl1;  mode = 0; break;
        case 2: W = Wn2;  mode = 0; break;
        case 3: W = Wl2;  mode = 0; break;
        case 4: W = tgW;  mode = 0; break;
        case 5: W = gateW; mode = 2; break;
        case 6: W = gateW; mode = 3; break;
        default: W = tdW; mode = 1; break;
    }
    unsigned char* base = g_Wpack[m];
    for (int idx = threadIdx.x; idx < 16384; idx += blockDim.x) {
        int k = idx >> 7, n = idx & 127;
        float v;
        if      (mode == 0) v = W[k * 128 + n];
        else if (mode == 1) v = W[n * 128 + k];
        else if (mode == 2) v = W[n * 256 + k];
        else                v = W[n * 256 + 128 + k];
        __nv_bfloat16 hi = __float2bfloat16(v);
        __nv_bfloat16 lo = __float2bfloat16(v - __bfloat162float(hi));
        uint32_t o = swz((uint32_t)(k * 256 + n * 2));
        *(__nv_bfloat16*)(base + o)         = hi;
        *(__nv_bfloat16*)(base + 32768 + o) = lo;
    }
}

// ---------------- l2norm ----------------
__global__ void l2norm_kernel(const float* __restrict__ in, float* __restrict__ out, int M) {
    int w = (blockIdx.x * blockDim.x + threadIdx.x) >> 5;
    int lane = threadIdx.x & 31;
    if (w >= M) return;
    float4 v = ((const float4*)in)[w*32 + lane];
    float ss = v.x*v.x + v.y*v.y + v.z*v.z + v.w*v.w;
    #pragma unroll
    for (int o = 16; o; o >>= 1) ss += __shfl_xor_sync(0xffffffffu, ss, o);
    float inv = 1.0f / fmaxf(sqrtf(ss), 1e-12f);
    v.x *= inv; v.y *= inv; v.z *= inv; v.w *= inv;
    ((float4*)out)[w*32 + lane] = v;
}

// ---------------- relation GRUCell ----------------
__global__ void gru_kernel(const float* __restrict__ emb_rel, const float* __restrict__ rel,
                           const float* __restrict__ Wx, const float* __restrict__ Wh,
                           const float* __restrict__ bx, const float* __restrict__ bh,
                           float* __restrict__ relOut) {
    __shared__ float s_x[8][256];
    int t = threadIdx.x;
    int row0 = blockIdx.x * 8;
    for (int i = t; i < 8*64; i += 128) {
        int rr = i >> 6, c4 = i & 63;
        int m = row0 + rr;
        float4 v = make_float4(0.f,0.f,0.f,0.f);
        if (m < NR2)
            v = (c4 < 32) ? ((const float4*)emb_rel)[m*32 + c4]
                          : ((const float4*)rel)[m*32 + (c4-32)];
        *(float4*)&s_x[rr][c4*4] = v;
    }
    __syncthreads();
    const float4* wr = (const float4*)(Wx + (      t)*256);
    const float4* wz = (const float4*)(Wx + (128 + t)*256);
    const float4* wn = (const float4*)(Wx + (256 + t)*256);
    const float4* vr = (const float4*)(Wh + (      t)*128);
    const float4* vz = (const float4*)(Wh + (128 + t)*128);
    const float4* vn = (const float4*)(Wh + (256 + t)*128);
    float bxr = bx[t], bxz = bx[128+t], bxn = bx[256+t];
    float bhr = bh[t], bhz = bh[128+t], bhn = bh[256+t];
    for (int rr = 0; rr < 8; rr++) {
        int m = row0 + rr;
        if (m >= NR2) break;
        float gxr = bxr, gxz = bxz, gxn = bxn;
        float ghr = bhr, ghz = bhz, ghn = bhn;
        #pragma unroll 8
        for (int k4 = 0; k4 < 64; k4++) {
            float4 x = *(float4*)&s_x[rr][k4*4];
            float4 a = wr[k4], b = wz[k4], c = wn[k4];
            gxr += x.x*a.x + x.y*a.y + x.z*a.z + x.w*a.w;
            gxz += x.x*b.x + x.y*b.y + x.z*b.z + x.w*b.w;
            gxn += x.x*c.x + x.y*c.y + x.z*c.z + x.w*c.w;
        }
        #pragma unroll 8
        for (int k4 = 0; k4 < 32; k4++) {
            float4 x = *(float4*)&s_x[rr][128 + k4*4];
            float4 a = vr[k4], b = vz[k4], c = vn[k4];
            ghr += x.x*a.x + x.y*a.y + x.z*a.z + x.w*a.w;
            ghz += x.x*b.x + x.y*b.y + x.z*b.z + x.w*b.w;
            ghn += x.x*c.x + x.y*c.y + x.z*c.z + x.w*c.w;
        }
        float r  = sigf(gxr + ghr);
        float z  = sigf(gxz + ghz);
        float nn = tanhf(gxn + r*ghn);
        float hp = s_x[rr][128 + t];
        relOut[m*128 + t] = (1.0f - z)*nn + z*hp;
    }
}

// ---------------- edge gather + vector-atomic scatter ----------------
__global__ void edge_kernel(const int* __restrict__ src, const int* __restrict__ dst,
                            const int* __restrict__ ety, const float* __restrict__ HW,
                            const float* __restrict__ R, float* __restrict__ agg,
                            float* __restrict__ deg, int E, int do_deg) {
    int e = (blockIdx.x * blockDim.x + threadIdx.x) >> 5;
    int lane = threadIdx.x & 31;
    if (e >= E) return;
    int s = __ldg(src + e), d = __ldg(dst + e), r = __ldg(ety + e);
    float4 v  = __ldg(((const float4*)HW) + s*32 + lane);
    float4 rv = __ldg(((const float4*)R)  + r*32 + lane);
    v.x += rv.x; v.y += rv.y; v.z += rv.z; v.w += rv.w;
    float* p = agg + (size_t)d*128 + lane*4;
    asm volatile("red.global.add.v4.f32 [%0], {%1,%2,%3,%4};"
                 :: "l"(p), "f"(v.x), "f"(v.y), "f"(v.z), "f"(v.w) : "memory");
    if (do_deg && lane == 0) atomicAdd(deg + d, 1.0f);
}

// ---------------- staging ----------------
__device__ __forceinline__ void stage_A_g(char* smc, int dstOff, const float* A,
                                          int row0, int M, int tid) {
    for (int i = tid; i < 2048; i += NTHR) {
        int r = i >> 4, c8 = i & 15;
        int gr = row0 + r;
        float4 v0 = make_float4(0.f,0.f,0.f,0.f), v1 = v0;
        if (gr < M) {
            v0 = __ldg(((const float4*)A) + (size_t)gr*32 + c8*2);
            v1 = __ldg(((const float4*)A) + (size_t)gr*32 + c8*2 + 1);
        }
        float f[8] = {v0.x, v0.y, v0.z, v0.w, v1.x, v1.y, v1.z, v1.w};
        __nv_bfloat162 hi[4], lo[4];
        #pragma unroll
        for (int q = 0; q < 4; q++) {
            __nv_bfloat16 hx = __float2bfloat16(f[2*q]);
            __nv_bfloat16 hy = __float2bfloat16(f[2*q+1]);
            hi[q].x = hx; hi[q].y = hy;
            lo[q].x = __float2bfloat16(f[2*q]   - __bfloat162float(hx));
            lo[q].y = __float2bfloat16(f[2*q+1] - __bfloat162float(hy));
        }
        uint32_t off = swz((uint32_t)(r*256 + c8*16));
        *(uint4*)(smc + dstOff + off)         = *(uint4*)hi;
        *(uint4*)(smc + dstOff + 32768 + off) = *(uint4*)lo;
    }
}
__device__ __forceinline__ void stage_W(uint32_t sb, int dstOff, const unsigned char* Wimg, int tid) {
    uint32_t s = sb + dstOff;
    #pragma unroll 2
    for (int i = tid; i < 4096; i += NTHR) cp16(s + i*16, Wimg + (size_t)i*16);
    asm volatile("cp.async.commit_group;");
}
__device__ __forceinline__ float2 readA2(const char* smc, int off, int row, int c) {
    uint32_t o = swz((uint32_t)(row*256 + c*2));
    __nv_bfloat162 h = *(const __nv_bfloat162*)(smc + off + o);
    __nv_bfloat162 l = *(const __nv_bfloat162*)(smc + off + 32768 + o);
    return make_float2(__bfloat162float(h.x) + __bfloat162float(l.x),
                       __bfloat162float(h.y) + __bfloat162float(l.y));
}
// fragments -> smem hi/lo (optionally minus reconstruction of subOff buffer)
__device__ __forceinline__ void stage_A_r(char* smc, int dstOff, const float hv[8][4],
                                          int lid, int wm, int wn, int subOff) {
    #pragma unroll
    for (int rr = 0; rr < 2; rr++) {
        int row = wm*16 + rr*8 + (lid >> 2);
        #pragma unroll
        for (int nj = 0; nj < 8; nj++) {
            int c = wn*64 + nj*8 + (lid & 3)*2;
            float v0 = hv[nj][rr*2], v1 = hv[nj][rr*2+1];
            if (subOff >= 0) {
                float2 s = readA2(smc, subOff, row, c);
                v0 -= s.x; v1 -= s.y;
            }
            __nv_bfloat16 h0 = __float2bfloat16(v0), h1 = __float2bfloat16(v1);
            __nv_bfloat162 hi2, lo2;
            hi2.x = h0; hi2.y = h1;
            lo2.x = __float2bfloat16(v0 - __bfloat162float(h0));
            lo2.y = __float2bfloat16(v1 - __bfloat162float(h1));
            uint32_t o = swz((uint32_t)(row*256 + c*2));
            *(__nv_bfloat162*)(smc + dstOff + o)         = hi2;
            *(__nv_bfloat162*)(smc + dstOff + 32768 + o) = lo2;
        }
    }
}

// ---------------- mainloop: warp tile 16x64, split-bf16 ----------------
__device__ __forceinline__ void gemm_tile(uint32_t sb, uint32_t aOff, uint32_t wOff,
                                          int lid, int wm, int wn, float acc[8][4]) {
    #pragma unroll
    for (int k0 = 0; k0 < 128; k0 += 16) {
        uint32_t aH[4], aL[4];
        {
            int row = wm*16 + (lid & 15);
            int col = k0 + ((lid >> 4) << 3);
            uint32_t off = swz((uint32_t)(row*256 + col*2));
            ldsm4(aH, sb + aOff + off);
            ldsm4(aL, sb + aOff + 32768 + off);
        }
        #pragma unroll
        for (int p = 0; p < 4; p++) {
            int krow = k0 + (lid & 15);
            int col  = wn*64 + p*16 + ((lid >> 4) << 3);
            uint32_t off = swz((uint32_t)(krow*256 + col*2));
            uint32_t bH[4], bL[4];
            ldsm4t(bH, sb + wOff + off);
            ldsm4t(bL, sb + wOff + 32768 + off);
            mma16816(acc[2*p],   aH, bH[0], bH[1]);
            mma16816(acc[2*p],   aL, bH[0], bH[1]);
            mma16816(acc[2*p],   aH, bL[0], bL[1]);
            mma16816(acc[2*p+1], aH, bH[2], bH[3]);
            mma16816(acc[2*p+1], aL, bH[2], bH[3]);
            mma16816(acc[2*p+1], aH, bL[2], bL[3]);
        }
    }
}
#define ZERO_ACC(acc) { _Pragma("unroll") for (int b_=0;b_<8;b_++) _Pragma("unroll") for (int c_=0;c_<4;c_++) acc[b_][c_]=0.0f; }

// plain writeout
__device__ __forceinline__ void write_plain(float* C, int M, int row0, int lid, int wm, int wn,
                                            const float acc[8][4]) {
    #pragma unroll
    for (int rr = 0; rr < 2; rr++) {
        int gr = row0 + wm*16 + rr*8 + (lid >> 2);
        if (gr >= M) continue;
        #pragma unroll
        for (int nj = 0; nj < 8; nj++) {
            int c = wn*64 + nj*8 + (lid & 3)*2;
            *(float2*)(C + (size_t)gr*128 + c) = make_float2(acc[nj][rr*2], acc[nj][rr*2+1]);
        }
    }
}

// ---------------- plain GEMM body ----------------
__device__ __forceinline__ void plain_body(const float* A, const unsigned char* Wimg,
                                           float* C, int M, int row0) {
    extern __shared__ char smc[];
    uint32_t sb = smem_u32(smc);
    int tid = threadIdx.x, wid = tid >> 5, lid = tid & 31;
    int wm = wid & 7, wn = wid >> 3;
    stage_W(sb, PG_W, Wimg, tid);
    stage_A_g(smc, PG_A, A, row0, M, tid);
    asm volatile("cp.async.wait_group 0;");
    __syncthreads();
    float acc[8][4]; ZERO_ACC(acc);
    gemm_tile(sb, PG_A, PG_W, lid, wm, wn, acc);
    write_plain(C, M, row0, lid, wm, wn, acc);
}

__global__ __launch_bounds__(NTHR, 1) void plain_gemm(
    const float* __restrict__ A, const unsigned char* __restrict__ Wimg,
    float* __restrict__ C, int M) {
    plain_body(A, Wimg, C, M, blockIdx.x * 128);
}

__global__ __launch_bounds__(NTHR, 1) void relpair_gemm(
    const float* __restrict__ rel,
    const unsigned char* __restrict__ pWn1, const unsigned char* __restrict__ pWn2,
    float* __restrict__ R1, float* __restrict__ R2) {
    int b = blockIdx.x;
    plain_body(rel, (b < 4) ? pWn1 : pWn2, (b < 4) ? R1 : R2, NR2, (b & 3) * 128);
}

// ---------------- K2: cur = FIN(h@Wl1, agg); HW = cur@Wn2 ----------------
__global__ __launch_bounds__(NTHR, 1) void k2_kernel(
    const float* __restrict__ h,
    const unsigned char* __restrict__ pWl1, const unsigned char* __restrict__ pWn2,
    float* __restrict__ cur, float* __restrict__ HW, int M,
    const float* __restrict__ agg, const float* __restrict__ deg)
{
    extern __shared__ char smc[];
    uint32_t sb = smem_u32(smc);
    int tid = threadIdx.x, wid = tid >> 5, lid = tid & 31;
    int wm = wid & 7, wn = wid >> 3;
    int row0 = blockIdx.x * 128;

    stage_W(sb, PG_W, pWl1, tid);
    stage_A_g(smc, PG_A, h, row0, M, tid);
    asm volatile("cp.async.wait_group 0;");
    __syncthreads();

    float acc[8][4]; ZERO_ACC(acc);
    gemm_tile(sb, PG_A, PG_W, lid, wm, wn, acc);

    // FIN epilogue -> hv (=cur fragments), write cur
    float hv[8][4];
    #pragma unroll
    for (int rr = 0; rr < 2; rr++) {
        int gr = row0 + wm*16 + rr*8 + (lid >> 2);
        bool rv = (gr < M);
        float invdeg = rv ? 1.0f / fmaxf(__ldg(deg + gr), 1.0f) : 1.0f;
        #pragma unroll
        for (int nj = 0; nj < 8; nj++) {
            int c = wn*64 + nj*8 + (lid & 3)*2;
            float2 ag = rv ? *(const float2*)(agg + (size_t)gr*128 + c) : make_float2(0.f,0.f);
            float o0 = fmaf(ag.x, invdeg, acc[nj][rr*2]);
            float o1 = fmaf(ag.y, invdeg, acc[nj][rr*2+1]);
            o0 = o0 >= 0.f ? o0 : SLOPE*o0;
            o1 = o1 >= 0.f ? o1 : SLOPE*o1;
            hv[nj][rr*2] = o0; hv[nj][rr*2+1] = o1;
            if (rv) *(float2*)(cur + (size_t)gr*128 + c) = make_float2(o0, o1);
        }
    }
    __syncthreads();

    // phase 2: HW = cur@Wn2
    stage_W(sb, PG_W, pWn2, tid);
    stage_A_r(smc, PG_A, hv, lid, wm, wn, -1);
    asm volatile("cp.async.wait_group 0;");
    __syncthreads();
    ZERO_ACC(acc);
    gemm_tile(sb, PG_A, PG_W, lid, wm, wn, acc);
    write_plain(HW, M, row0, lid, wm, wn, acc);
}

// ---------------- K3: FINNORM + time-gate + gated fusion + tdiff (+ next h@Wn1) ----------------
__global__ __launch_bounds__(NTHR, 1) void k3_kernel(
    const float* __restrict__ cur, const float* __restrict__ h,
    const unsigned char* __restrict__ pWl2, const unsigned char* __restrict__ pTg,
    const unsigned char* __restrict__ pGa,  const unsigned char* __restrict__ pGb,
    const unsigned char* __restrict__ pTd,  const unsigned char* __restrict__ pWn1,
    const float* __restrict__ tgb, const float* __restrict__ gateb,
    const float* __restrict__ tdb,
    const float* __restrict__ agg, const float* __restrict__ deg,
    float* __restrict__ hout, float* __restrict__ HWout, int M, int doHW)
{
    extern __shared__ char smc[];
    uint32_t sb = smem_u32(smc);
    int tid = threadIdx.x, wid = tid >> 5, lid = tid & 31;
    int wm = wid & 7, wn = wid >> 3;
    int row0 = blockIdx.x * 128;

    if (tid < 128) {
        ((float*)(smc + K3_BTG))[tid] = __ldg(tgb + tid);
        ((float*)(smc + K3_BGA))[tid] = __ldg(gateb + tid);
        ((float*)(smc + K3_BTD))[tid] = __ldg(tdb + tid);
    }
    stage_W(sb, K3_W, pWl2, tid);
    stage_A_g(smc, K3_A1, cur, row0, M, tid);
    stage_A_g(smc, K3_A2, h,   row0, M, tid);
    asm volatile("cp.async.wait_group 0;");
    __syncthreads();

    const float* btg = (const float*)(smc + K3_BTG);
    const float* bga = (const float*)(smc + K3_BGA);
    const float* btd = (const float*)(smc + K3_BTD);
    float* sred = (float*)(smc + K3_SRED);

    float acc[8][4], hv[8][4];

    // ---- phase 0: nrm = l2norm(leaky(agg/deg + cur@Wl2)) ----
    ZERO_ACC(acc);
    gemm_tile(sb, K3_A1, K3_W, lid, wm, wn, acc);
    #pragma unroll
    for (int rr = 0; rr < 2; rr++) {
        int row = wm*16 + rr*8 + (lid >> 2);
        int gr = row0 + row;
        bool rv = (gr < M);
        float invdeg = rv ? 1.0f / fmaxf(__ldg(deg + gr), 1.0f) : 1.0f;
        float ss = 0.0f;
        #pragma unroll
        for (int nj = 0; nj < 8; nj++) {
            int c = wn*64 + nj*8 + (lid & 3)*2;
            float2 ag = rv ? *(const float2*)(agg + (size_t)gr*128 + c) : make_float2(0.f,0.f);
            float o0 = fmaf(ag.x, invdeg, acc[nj][rr*2]);
            float o1 = fmaf(ag.y, invdeg, acc[nj][rr*2+1]);
            o0 = o0 >= 0.f ? o0 : SLOPE*o0;
            o1 = o1 >= 0.f ? o1 : SLOPE*o1;
            hv[nj][rr*2] = o0; hv[nj][rr*2+1] = o1;
            ss += o0*o0 + o1*o1;
        }
        ss += __shfl_xor_sync(0xffffffffu, ss, 1);
        ss += __shfl_xor_sync(0xffffffffu, ss, 2);
        if ((lid & 3) == 0) sred[wn*128 + row] = ss;
    }
    __syncthreads();
    #pragma unroll
    for (int rr = 0; rr < 2; rr++) {
        int row = wm*16 + rr*8 + (lid >> 2);
        float inv = 1.0f / fmaxf(sqrtf(sred[row] + sred[128 + row]), 1e-12f);
        #pragma unroll
        for (int nj = 0; nj < 8; nj++) { hv[nj][rr*2] *= inv; hv[nj][rr*2+1] *= inv; }
    }
    __syncthreads();

    // ---- phase 1: time gate  hn1 = sig(nrm@Tg + btg)*nrm + (1-g)*h ----
    stage_W(sb, K3_W, pTg, tid);
    stage_A_r(smc, K3_A1, hv, lid, wm, wn, -1);
    asm volatile("cp.async.wait_group 0;");
    __syncthreads();
    ZERO_ACC(acc);
    gemm_tile(sb, K3_A1, K3_W, lid, wm, wn, acc);
    #pragma unroll
    for (int rr = 0; rr < 2; rr++) {
        int row = wm*16 + rr*8 + (lid >> 2);
        #pragma unroll
        for (int nj = 0; nj < 8; nj++) {
            int c = wn*64 + nj*8 + (lid & 3)*2;
            float2 nv = readA2(smc, K3_A1, row, c);
            float2 hh = readA2(smc, K3_A2, row, c);
            float g0 = sigf(acc[nj][rr*2]   + btg[c]);
            float g1 = sigf(acc[nj][rr*2+1] + btg[c+1]);
            hv[nj][rr*2]   = g0*nv.x + (1.f-g0)*hh.x;
            hv[nj][rr*2+1] = g1*nv.y + (1.f-g1)*hh.y;
        }
    }
    __syncthreads();

    // ---- phase 2: gated fusion  hn2 = sig(hn1@Ga + h@Gb + bga)*hn1 + (1-g)*h ----
    stage_W(sb, K3_W, pGa, tid);
    stage_A_r(smc, K3_A1, hv, lid, wm, wn, -1);
    asm volatile("cp.async.wait_group 0;");
    __syncthreads();
    ZERO_ACC(acc);
    gemm_tile(sb, K3_A1, K3_W, lid, wm, wn, acc);
    __syncthreads();
    stage_W(sb, K3_W, pGb, tid);
    asm volatile("cp.async.wait_group 0;");
    __syncthreads();
    gemm_tile(sb, K3_A2, K3_W, lid, wm, wn, acc);
    #pragma unroll
    for (int rr = 0; rr < 2; rr++) {
        int row = wm*16 + rr*8 + (lid >> 2);
        #pragma unroll
        for (int nj = 0; nj < 8; nj++) {
            int c = wn*64 + nj*8 + (lid & 3)*2;
            float2 hh = readA2(smc, K3_A2, row, c);
            float g0 = sigf(acc[nj][rr*2]   + bga[c]);
            float g1 = sigf(acc[nj][rr*2+1] + bga[c+1]);
            hv[nj][rr*2]   = g0*hv[nj][rr*2]   + (1.f-g0)*hh.x;
            hv[nj][rr*2+1] = g1*hv[nj][rr*2+1] + (1.f-g1)*hh.y;
        }
    }
    __syncthreads();

    // ---- phase 3: tdiff  h_next = hn2 + relu((hn2-h)@Td + btd) ----
    stage_W(sb, K3_W, pTd, tid);
    stage_A_r(smc, K3_A1, hv, lid, wm, wn, K3_A2);   // stage (hn2 - h)
    asm volatile("cp.async.wait_group 0;");
    __syncthreads();
    ZERO_ACC(acc);
    gemm_tile(sb, K3_A1, K3_W, lid, wm, wn, acc);
    #pragma unroll
    for (int rr = 0; rr < 2; rr++) {
        int gr = row0 + wm*16 + rr*8 + (lid >> 2);
        bool rv = (gr < M);
        #pragma unroll
        for (int nj = 0; nj < 8; nj++) {
            int c = wn*64 + nj*8 + (lid & 3)*2;
            float y0 = fmaxf(acc[nj][rr*2]   + btd[c],   0.f);
            float y1 = fmaxf(acc[nj][rr*2+1] + btd[c+1], 0.f);
            hv[nj][rr*2]   += y0;
            hv[nj][rr*2+1] += y1;
            if (rv) *(float2*)(hout + (size_t)gr*128 + c) =
                        make_float2(hv[nj][rr*2], hv[nj][rr*2+1]);
        }
    }

    // ---- phase 4 (optional): HW_next = h_next@Wn1 ----
    if (doHW) {
        __syncthreads();
        stage_W(sb, K3_W, pWn1, tid);
        stage_A_r(smc, K3_A1, hv, lid, wm, wn, -1);
        asm volatile("cp.async.wait_group 0;");
        __syncthreads();
        ZERO_ACC(acc);
        gemm_tile(sb, K3_A1, K3_W, lid, wm, wn, acc);
        write_plain(HWout, M, row0, lid, wm, wn, acc);
    }
}

// ---------------- host driver ----------------
extern "C" void kernel_launch(void* const* d_in, const int* in_sizes, int n_in,
                              void* d_out, int out_size) {
    const int*   src     = (const int*)d_in[0];
    const int*   dst     = (const int*)d_in[1];
    const int*   ety     = (const int*)d_in[2];
    const float* dyn     = (const float*)d_in[3];
    const float* emb_rel = (const float*)d_in[4];
    const float* Wn1     = (const float*)d_in[5];
    const float* Wl1     = (const float*)d_in[6];
    const float* Wn2     = (const float*)d_in[7];
    const float* Wl2     = (const float*)d_in[8];
    const float* gWx     = (const float*)d_in[9];
    const float* gWh     = (const float*)d_in[10];
    const float* gbx     = (const float*)d_in[11];
    const float* gbh     = (const float*)d_in[12];
    const float* gateW   = (const float*)d_in[13];
    const float* gateb   = (const float*)d_in[14];
    const float* tdW     = (const float*)d_in[15];
    const float* tdb     = (const float*)d_in[16];
    const float* tgW     = (const float*)d_in[17];
    const float* tgb     = (const float*)d_in[18];
    float* out = (float*)d_out;

    float *hA,*hB,*cur,*HW,*agg,*deg,*relA,*relB,*R1,*R2;
    unsigned char* Wp;
    cudaGetSymbolAddress((void**)&hA,  g_hA);
    cudaGetSymbolAddress((void**)&hB,  g_hB);
    cudaGetSymbolAddress((void**)&cur, g_cur);
    cudaGetSymbolAddress((void**)&HW,  g_HW);
    cudaGetSymbolAddress((void**)&agg, g_agg);
    cudaGetSymbolAddress((void**)&deg, g_deg);
    cudaGetSymbolAddress((void**)&relA,g_relA);
    cudaGetSymbolAddress((void**)&relB,g_relB);
    cudaGetSymbolAddress((void**)&R1,  g_R1);
    cudaGetSymbolAddress((void**)&R2,  g_R2);
    cudaGetSymbolAddress((void**)&Wp,  g_Wpack);

    cudaFuncSetAttribute((const void*)plain_gemm,   cudaFuncAttributeMaxDynamicSharedMemorySize, PG_SIZE);
    cudaFuncSetAttribute((const void*)relpair_gemm, cudaFuncAttributeMaxDynamicSharedMemorySize, PG_SIZE);
    cudaFuncSetAttribute((const void*)k2_kernel,    cudaFuncAttributeMaxDynamicSharedMemorySize, PG_SIZE);
    cudaFuncSetAttribute((const void*)k3_kernel,    cudaFuncAttributeMaxDynamicSharedMemorySize, K3_SIZE);

    const unsigned char* pWn1 = Wp + 0*65536;
    const unsigned char* pWl1 = Wp + 1*65536;
    const unsigned char* pWn2 = Wp + 2*65536;
    const unsigned char* pWl2 = Wp + 3*65536;
    const unsigned char* pTg  = Wp + 4*65536;
    const unsigned char* pGa  = Wp + 5*65536;
    const unsigned char* pGb  = Wp + 6*65536;
    const unsigned char* pTd  = Wp + 7*65536;

    const int GB = (NENT + 127) / 128;   // 782
    const int EB = (EE*32 + 255) / 256;

    pack_kernel<<<8, 256>>>(Wn1, Wl1, Wn2, Wl2, tgW, gateW, tdW);
    l2norm_kernel<<<(NENT + 7)/8, 256>>>(dyn, hA, NENT);
    // initial HW = h0 @ Wn1
    plain_gemm<<<GB, NTHR, PG_SIZE>>>(hA, pWn1, HW, NENT);

    const float* relPrev = emb_rel;
    float* relBufs[2] = { relB, relA };
    float* h     = hA;
    float* hnext = hB;

    for (int t = 0; t < TT; t++) {
        const int* sT = src + t*EE;
        const int* dT = dst + t*EE;
        const int* eT = ety + t*EE;
        float* relNext = relBufs[t & 1];

        cudaMemsetAsync(agg, 0, (size_t)NENT*HDIM*sizeof(float));
        cudaMemsetAsync(deg, 0, (size_t)NENT*sizeof(float));

        gru_kernel<<<(NR2 + 7)/8, 128>>>(emb_rel, relPrev, gWx, gWh, gbx, gbh, relNext);
        relpair_gemm<<<8, NTHR, PG_SIZE>>>(relNext, pWn1, pWn2, R1, R2);

        // layer 1: edge on HW (h@Wn1), then cur = FIN, HW <- cur@Wn2 (fused)
        edge_kernel<<<EB, 256>>>(sT, dT, eT, HW, R1, agg, deg, EE, 1);
        k2_kernel<<<GB, NTHR, PG_SIZE>>>(h, pWl1, pWn2, cur, HW, NENT, agg, deg);

        // layer 2 edge
        cudaMemsetAsync(agg, 0, (size_t)NENT*HDIM*sizeof(float));
        edge_kernel<<<EB, 256>>>(sT, dT, eT, HW, R2, agg, deg, EE, 0);

        // K3: FINNORM + tail (+ next HW)
        float* target = (t == TT-1) ? out : hnext;
        k3_kernel<<<GB, NTHR, K3_SIZE>>>(cur, h, pWl2, pTg, pGa, pGb, pTd, pWn1,
                                         tgb, gateb, tdb, agg, deg,
                                         target, HW, NENT, (t < TT-1) ? 1 : 0);

        relPrev = relNext;
        if (t < TT-1) { float* tmp = h; h = hnext; hnext = tmp; }
    }
}

// round 8
// speedup vs baseline: 2.5304x; 1.1850x over previous
#include <cuda_runtime.h>
#include <cuda_bf16.h>
#include <cstdint>
#include <math.h>

// ---------------- problem constants ----------------
#define NENT   100000
#define HDIM   128
#define NR2    460
#define TT     4
#define EE     200000
#define SLOPE  0.22916666666666666f
#define NTHR   512

// ---- smem layouts ----
#define PG_A     2048
#define PG_W     (PG_A + 65536)
#define PG_SIZE  (PG_W + 65536)          // 133120
// K3 (biases are 128 floats each; sred 256 floats ends at 2560 < A1)
#define K3_BTG   0
#define K3_BGA   512
#define K3_BTD   1024
#define K3_SRED  1536
#define K3_A1    4096
#define K3_A2    (K3_A1 + 65536)
#define K3_W     (K3_A2 + 65536)
#define K3_SIZE  (K3_W + 65536)          // 200704
// GRU biases (384 floats each; ends at 3072 < A1)
#define GR_BX    0
#define GR_BH    1536

// ---------------- scratch ----------------
__device__ float g_hA [NENT*HDIM];
__device__ float g_hB [NENT*HDIM];
__device__ float g_cur[NENT*HDIM];
__device__ float g_HW [NENT*HDIM];
__device__ float g_agg[NENT*HDIM];
__device__ float g_deg[NENT];
__device__ float g_relA[NR2*HDIM];
__device__ float g_relB[NR2*HDIM];
__device__ float g_R1 [NR2*HDIM];
__device__ float g_R2 [NR2*HDIM];
// [0..7] layer/tail weights, [8..13] WxT (gate g, ktile kt), [14..16] WhT (gate g)
__device__ unsigned char g_Wpack[17][65536];

__device__ __forceinline__ float sigf(float x) { return 1.0f / (1.0f + __expf(-x)); }

__device__ __forceinline__ uint32_t smem_u32(const void* p) {
    uint32_t a;
    asm("{ .reg .u64 t; cvta.to.shared.u64 t, %1; cvt.u32.u64 %0, t; }" : "=r"(a) : "l"(p));
    return a;
}
__device__ __host__ __forceinline__ uint32_t swz(uint32_t off) {
    return off ^ ((off >> 4) & 0x70);
}
__device__ __forceinline__ void ldsm4(uint32_t* r, uint32_t a) {
    asm volatile("ldmatrix.sync.aligned.m8n8.x4.shared.b16 {%0,%1,%2,%3}, [%4];"
                 : "=r"(r[0]),"=r"(r[1]),"=r"(r[2]),"=r"(r[3]) : "r"(a));
}
__device__ __forceinline__ void ldsm4t(uint32_t* r, uint32_t a) {
    asm volatile("ldmatrix.sync.aligned.m8n8.x4.trans.shared.b16 {%0,%1,%2,%3}, [%4];"
                 : "=r"(r[0]),"=r"(r[1]),"=r"(r[2]),"=r"(r[3]) : "r"(a));
}
__device__ __forceinline__ void mma16816(float* d, const uint32_t* a, uint32_t b0, uint32_t b1) {
    asm volatile("mma.sync.aligned.m16n8k16.row.col.f32.bf16.bf16.f32 "
                 "{%0,%1,%2,%3},{%4,%5,%6,%7},{%8,%9},{%0,%1,%2,%3};"
                 : "+f"(d[0]),"+f"(d[1]),"+f"(d[2]),"+f"(d[3])
                 : "r"(a[0]),"r"(a[1]),"r"(a[2]),"r"(a[3]),"r"(b0),"r"(b1));
}
__device__ __forceinline__ void cp16(uint32_t saddr, const void* gaddr) {
    asm volatile("cp.async.cg.shared.global [%0], [%1], 16;" :: "r"(saddr), "l"(gaddr));
}

// ---------------- weight pack ----------------
__global__ void pack_kernel(const float* __restrict__ Wn1, const float* __restrict__ Wl1,
                            const float* __restrict__ Wn2, const float* __restrict__ Wl2,
                            const float* __restrict__ tgW, const float* __restrict__ gateW,
                            const float* __restrict__ tdW,
                            const float* __restrict__ gWx, const float* __restrict__ gWh) {
    int m = blockIdx.x;
    unsigned char* base = g_Wpack[m];
    for (int idx = threadIdx.x; idx < 16384; idx += blockDim.x) {
        int k = idx >> 7, n = idx & 127;
        float v;
        if      (m == 0) v = Wn1[k * 128 + n];
        else if (m == 1) v = Wl1[k * 128 + n];
        else if (m == 2) v = Wn2[k * 128 + n];
        else if (m == 3) v = Wl2[k * 128 + n];
        else if (m == 4) v = tgW[k * 128 + n];
        else if (m == 5) v = gateW[n * 256 + k];
        else if (m == 6) v = gateW[n * 256 + 128 + k];
        else if (m == 7) v = tdW[n * 128 + k];
        else if (m < 14) {                     // WxT: g=(m-8)>>1, kt=(m-8)&1
            int g = (m - 8) >> 1, kt = (m - 8) & 1;
            v = gWx[(g * 128 + n) * 256 + kt * 128 + k];
        } else {                               // WhT: g=m-14
            int g = m - 14;
            v = gWh[(g * 128 + n) * 128 + k];
        }
        __nv_bfloat16 hi = __float2bfloat16(v);
        __nv_bfloat16 lo = __float2bfloat16(v - __bfloat162float(hi));
        uint32_t o = swz((uint32_t)(k * 256 + n * 2));
        *(__nv_bfloat16*)(base + o)         = hi;
        *(__nv_bfloat16*)(base + 32768 + o) = lo;
    }
}

// ---------------- l2norm ----------------
__global__ void l2norm_kernel(const float* __restrict__ in, float* __restrict__ out, int M) {
    int w = (blockIdx.x * blockDim.x + threadIdx.x) >> 5;
    int lane = threadIdx.x & 31;
    if (w >= M) return;
    float4 v = ((const float4*)in)[w*32 + lane];
    float ss = v.x*v.x + v.y*v.y + v.z*v.z + v.w*v.w;
    #pragma unroll
    for (int o = 16; o; o >>= 1) ss += __shfl_xor_sync(0xffffffffu, ss, o);
    float inv = 1.0f / fmaxf(sqrtf(ss), 1e-12f);
    v.x *= inv; v.y *= inv; v.z *= inv; v.w *= inv;
    ((float4*)out)[w*32 + lane] = v;
}

// ---------------- edge gather + vector-atomic scatter ----------------
__global__ void edge_kernel(const int* __restrict__ src, const int* __restrict__ dst,
                            const int* __restrict__ ety, const float* __restrict__ HW,
                            const float* __restrict__ R, float* __restrict__ agg,
                            float* __restrict__ deg, int E, int do_deg) {
    int e = (blockIdx.x * blockDim.x + threadIdx.x) >> 5;
    int lane = threadIdx.x & 31;
    if (e >= E) return;
    int s = __ldg(src + e), d = __ldg(dst + e), r = __ldg(ety + e);
    float4 v  = __ldg(((const float4*)HW) + s*32 + lane);
    float4 rv = __ldg(((const float4*)R)  + r*32 + lane);
    v.x += rv.x; v.y += rv.y; v.z += rv.z; v.w += rv.w;
    float* p = agg + (size_t)d*128 + lane*4;
    asm volatile("red.global.add.v4.f32 [%0], {%1,%2,%3,%4};"
                 :: "l"(p), "f"(v.x), "f"(v.y), "f"(v.z), "f"(v.w) : "memory");
    if (do_deg && lane == 0) atomicAdd(deg + d, 1.0f);
}

// ---------------- staging ----------------
__device__ __forceinline__ void stage_A_g(char* smc, int dstOff, const float* A,
                                          int row0, int M, int tid) {
    for (int i = tid; i < 2048; i += NTHR) {
        int r = i >> 4, c8 = i & 15;
        int gr = row0 + r;
        float4 v0 = make_float4(0.f,0.f,0.f,0.f), v1 = v0;
        if (gr < M) {
            v0 = __ldg(((const float4*)A) + (size_t)gr*32 + c8*2);
            v1 = __ldg(((const float4*)A) + (size_t)gr*32 + c8*2 + 1);
        }
        float f[8] = {v0.x, v0.y, v0.z, v0.w, v1.x, v1.y, v1.z, v1.w};
        __nv_bfloat162 hi[4], lo[4];
        #pragma unroll
        for (int q = 0; q < 4; q++) {
            __nv_bfloat16 hx = __float2bfloat16(f[2*q]);
            __nv_bfloat16 hy = __float2bfloat16(f[2*q+1]);
            hi[q].x = hx; hi[q].y = hy;
            lo[q].x = __float2bfloat16(f[2*q]   - __bfloat162float(hx));
            lo[q].y = __float2bfloat16(f[2*q+1] - __bfloat162float(hy));
        }
        uint32_t off = swz((uint32_t)(r*256 + c8*16));
        *(uint4*)(smc + dstOff + off)         = *(uint4*)hi;
        *(uint4*)(smc + dstOff + 32768 + off) = *(uint4*)lo;
    }
}
__device__ __forceinline__ void stage_W(uint32_t sb, int dstOff, const unsigned char* Wimg, int tid) {
    uint32_t s = sb + dstOff;
    #pragma unroll 2
    for (int i = tid; i < 4096; i += NTHR) cp16(s + i*16, Wimg + (size_t)i*16);
    asm volatile("cp.async.commit_group;");
}
__device__ __forceinline__ float2 readA2(const char* smc, int off, int row, int c) {
    uint32_t o = swz((uint32_t)(row*256 + c*2));
    __nv_bfloat162 h = *(const __nv_bfloat162*)(smc + off + o);
    __nv_bfloat162 l = *(const __nv_bfloat162*)(smc + off + 32768 + o);
    return make_float2(__bfloat162float(h.x) + __bfloat162float(l.x),
                       __bfloat162float(h.y) + __bfloat162float(l.y));
}
__device__ __forceinline__ void stage_A_r(char* smc, int dstOff, const float hv[8][4],
                                          int lid, int wm, int wn, int subOff) {
    #pragma unroll
    for (int rr = 0; rr < 2; rr++) {
        int row = wm*16 + rr*8 + (lid >> 2);
        #pragma unroll
        for (int nj = 0; nj < 8; nj++) {
            int c = wn*64 + nj*8 + (lid & 3)*2;
            float v0 = hv[nj][rr*2], v1 = hv[nj][rr*2+1];
            if (subOff >= 0) {
                float2 s = readA2(smc, subOff, row, c);
                v0 -= s.x; v1 -= s.y;
            }
            __nv_bfloat16 h0 = __float2bfloat16(v0), h1 = __float2bfloat16(v1);
            __nv_bfloat162 hi2, lo2;
            hi2.x = h0; hi2.y = h1;
            lo2.x = __float2bfloat16(v0 - __bfloat162float(h0));
            lo2.y = __float2bfloat16(v1 - __bfloat162float(h1));
            uint32_t o = swz((uint32_t)(row*256 + c*2));
            *(__nv_bfloat162*)(smc + dstOff + o)         = hi2;
            *(__nv_bfloat162*)(smc + dstOff + 32768 + o) = lo2;
        }
    }
}

// ---------------- mainloop: warp tile 16x64, split-bf16 ----------------
__device__ __forceinline__ void gemm_tile(uint32_t sb, uint32_t aOff, uint32_t wOff,
                                          int lid, int wm, int wn, float acc[8][4]) {
    #pragma unroll
    for (int k0 = 0; k0 < 128; k0 += 16) {
        uint32_t aH[4], aL[4];
        {
            int row = wm*16 + (lid & 15);
            int col = k0 + ((lid >> 4) << 3);
            uint32_t off = swz((uint32_t)(row*256 + col*2));
            ldsm4(aH, sb + aOff + off);
            ldsm4(aL, sb + aOff + 32768 + off);
        }
        #pragma unroll
        for (int p = 0; p < 4; p++) {
            int krow = k0 + (lid & 15);
            int col  = wn*64 + p*16 + ((lid >> 4) << 3);
            uint32_t off = swz((uint32_t)(krow*256 + col*2));
            uint32_t bH[4], bL[4];
            ldsm4t(bH, sb + wOff + off);
            ldsm4t(bL, sb + wOff + 32768 + off);
            mma16816(acc[2*p],   aH, bH[0], bH[1]);
            mma16816(acc[2*p],   aL, bH[0], bH[1]);
            mma16816(acc[2*p],   aH, bL[0], bL[1]);
            mma16816(acc[2*p+1], aH, bH[2], bH[3]);
            mma16816(acc[2*p+1], aL, bH[2], bH[3]);
            mma16816(acc[2*p+1], aH, bL[2], bL[3]);
        }
    }
}
#define ZERO_ACC(acc) { _Pragma("unroll") for (int b_=0;b_<8;b_++) _Pragma("unroll") for (int c_=0;c_<4;c_++) acc[b_][c_]=0.0f; }

__device__ __forceinline__ void write_plain(float* C, int M, int row0, int lid, int wm, int wn,
                                            const float acc[8][4]) {
    #pragma unroll
    for (int rr = 0; rr < 2; rr++) {
        int gr = row0 + wm*16 + rr*8 + (lid >> 2);
        if (gr >= M) continue;
        #pragma unroll
        for (int nj = 0; nj < 8; nj++) {
            int c = wn*64 + nj*8 + (lid & 3)*2;
            *(float2*)(C + (size_t)gr*128 + c) = make_float2(acc[nj][rr*2], acc[nj][rr*2+1]);
        }
    }
}

// ---------------- plain GEMM ----------------
__global__ __launch_bounds__(NTHR, 1) void plain_gemm(
    const float* __restrict__ A, const unsigned char* __restrict__ Wimg,
    float* __restrict__ C, int M) {
    extern __shared__ char smc[];
    uint32_t sb = smem_u32(smc);
    int tid = threadIdx.x, wid = tid >> 5, lid = tid & 31;
    int wm = wid & 7, wn = wid >> 3;
    int row0 = blockIdx.x * 128;
    stage_W(sb, PG_W, Wimg, tid);
    stage_A_g(smc, PG_A, A, row0, M, tid);
    asm volatile("cp.async.wait_group 0;");
    __syncthreads();
    float acc[8][4]; ZERO_ACC(acc);
    gemm_tile(sb, PG_A, PG_W, lid, wm, wn, acc);
    write_plain(C, M, row0, lid, wm, wn, acc);
}

// ---------------- GRU via MMA + fused R1/R2 ----------------
__global__ __launch_bounds__(NTHR, 1) void gru_mma(
    const float* __restrict__ emb_rel, const float* __restrict__ rel,
    const unsigned char* __restrict__ Wp,
    const float* __restrict__ bx, const float* __restrict__ bh,
    float* __restrict__ relOut, float* __restrict__ R1, float* __restrict__ R2)
{
    extern __shared__ char smc[];
    uint32_t sb = smem_u32(smc);
    int tid = threadIdx.x, wid = tid >> 5, lid = tid & 31;
    int wm = wid & 7, wn = wid >> 3;
    int row0 = blockIdx.x * 128;

    float* sbx = (float*)(smc + GR_BX);    // 384 floats, bytes 0..1535
    float* sbh = (float*)(smc + GR_BH);    // 384 floats, bytes 1536..3071 (< A1@4096)
    if (tid < 384) { sbx[tid] = __ldg(bx + tid); sbh[tid] = __ldg(bh + tid); }

    stage_W(sb, K3_W, Wp + (8 + 2*1 + 0)*65536, tid);    // Wx z, kt0
    stage_A_g(smc, K3_A1, emb_rel, row0, NR2, tid);
    stage_A_g(smc, K3_A2, rel,     row0, NR2, tid);
    asm volatile("cp.async.wait_group 0;");
    __syncthreads();

    float acc[8][4], zg[8][4], rg[8][4];

    // ---- z gate ----
    ZERO_ACC(acc);
    gemm_tile(sb, K3_A1, K3_W, lid, wm, wn, acc);
    __syncthreads();
    stage_W(sb, K3_W, Wp + (8 + 2*1 + 1)*65536, tid);
    asm volatile("cp.async.wait_group 0;");
    __syncthreads();
    gemm_tile(sb, K3_A2, K3_W, lid, wm, wn, acc);
    __syncthreads();
    stage_W(sb, K3_W, Wp + (14 + 1)*65536, tid);
    asm volatile("cp.async.wait_group 0;");
    __syncthreads();
    gemm_tile(sb, K3_A2, K3_W, lid, wm, wn, acc);
    #pragma unroll
    for (int rr = 0; rr < 2; rr++)
        #pragma unroll
        for (int nj = 0; nj < 8; nj++) {
            int c = wn*64 + nj*8 + (lid & 3)*2;
            zg[nj][rr*2]   = sigf(acc[nj][rr*2]   + sbx[128+c]   + sbh[128+c]);
            zg[nj][rr*2+1] = sigf(acc[nj][rr*2+1] + sbx[128+c+1] + sbh[128+c+1]);
        }
    __syncthreads();

    // ---- r gate ----
    stage_W(sb, K3_W, Wp + (8 + 0)*65536, tid);
    asm volatile("cp.async.wait_group 0;");
    __syncthreads();
    ZERO_ACC(acc);
    gemm_tile(sb, K3_A1, K3_W, lid, wm, wn, acc);
    __syncthreads();
    stage_W(sb, K3_W, Wp + (8 + 1)*65536, tid);
    asm volatile("cp.async.wait_group 0;");
    __syncthreads();
    gemm_tile(sb, K3_A2, K3_W, lid, wm, wn, acc);
    __syncthreads();
    stage_W(sb, K3_W, Wp + 14*65536, tid);
    asm volatile("cp.async.wait_group 0;");
    __syncthreads();
    gemm_tile(sb, K3_A2, K3_W, lid, wm, wn, acc);
    #pragma unroll
    for (int rr = 0; rr < 2; rr++)
        #pragma unroll
        for (int nj = 0; nj < 8; nj++) {
            int c = wn*64 + nj*8 + (lid & 3)*2;
            rg[nj][rr*2]   = sigf(acc[nj][rr*2]   + sbx[c]   + sbh[c]);
            rg[nj][rr*2+1] = sigf(acc[nj][rr*2+1] + sbx[c+1] + sbh[c+1]);
        }
    __syncthreads();

    // ---- n gate ----
    stage_W(sb, K3_W, Wp + (8 + 2*2)*65536, tid);
    asm volatile("cp.async.wait_group 0;");
    __syncthreads();
    ZERO_ACC(acc);
    gemm_tile(sb, K3_A1, K3_W, lid, wm, wn, acc);
    __syncthreads();
    stage_W(sb, K3_W, Wp + (8 + 2*2 + 1)*65536, tid);
    asm volatile("cp.async.wait_group 0;");
    __syncthreads();
    gemm_tile(sb, K3_A2, K3_W, lid, wm, wn, acc);
    __syncthreads();
    stage_W(sb, K3_W, Wp + 16*65536, tid);
    asm volatile("cp.async.wait_group 0;");
    __syncthreads();
    float acch[8][4]; ZERO_ACC(acch);
    gemm_tile(sb, K3_A2, K3_W, lid, wm, wn, acch);

    // combine
    #pragma unroll
    for (int rr = 0; rr < 2; rr++) {
        int row = wm*16 + rr*8 + (lid >> 2);
        #pragma unroll
        for (int nj = 0; nj < 8; nj++) {
            int c = wn*64 + nj*8 + (lid & 3)*2;
            float2 hp = readA2(smc, K3_A2, row, c);
            float xn0 = acc[nj][rr*2]   + sbx[256+c];
            float xn1 = acc[nj][rr*2+1] + sbx[256+c+1];
            float hn0 = acch[nj][rr*2]   + sbh[256+c];
            float hn1 = acch[nj][rr*2+1] + sbh[256+c+1];
            float n0 = tanhf(xn0 + rg[nj][rr*2]  *hn0);
            float n1 = tanhf(xn1 + rg[nj][rr*2+1]*hn1);
            float z0 = zg[nj][rr*2], z1 = zg[nj][rr*2+1];
            float o0 = (1.f-z0)*n0 + z0*hp.x;
            float o1 = (1.f-z1)*n1 + z1*hp.y;
            zg[nj][rr*2] = o0; zg[nj][rr*2+1] = o1;
            int gr = row0 + row;
            if (gr < NR2) *(float2*)(relOut + (size_t)gr*128 + c) = make_float2(o0, o1);
        }
    }
    __syncthreads();

    // ---- R1 = relNext@Wn1, R2 = relNext@Wn2 ----
    stage_W(sb, K3_W, Wp + 0*65536, tid);
    stage_A_r(smc, K3_A1, zg, lid, wm, wn, -1);
    asm volatile("cp.async.wait_group 0;");
    __syncthreads();
    ZERO_ACC(acc);
    gemm_tile(sb, K3_A1, K3_W, lid, wm, wn, acc);
    write_plain(R1, NR2, row0, lid, wm, wn, acc);
    __syncthreads();
    stage_W(sb, K3_W, Wp + 2*65536, tid);
    asm volatile("cp.async.wait_group 0;");
    __syncthreads();
    ZERO_ACC(acc);
    gemm_tile(sb, K3_A1, K3_W, lid, wm, wn, acc);
    write_plain(R2, NR2, row0, lid, wm, wn, acc);
}

// ---------------- K2: cur = FIN(h@Wl1, agg); HW = cur@Wn2 ----------------
__global__ __launch_bounds__(NTHR, 1) void k2_kernel(
    const float* __restrict__ h,
    const unsigned char* __restrict__ pWl1, const unsigned char* __restrict__ pWn2,
    float* __restrict__ cur, float* __restrict__ HW, int M,
    const float* __restrict__ agg, const float* __restrict__ deg)
{
    extern __shared__ char smc[];
    uint32_t sb = smem_u32(smc);
    int tid = threadIdx.x, wid = tid >> 5, lid = tid & 31;
    int wm = wid & 7, wn = wid >> 3;
    int row0 = blockIdx.x * 128;

    stage_W(sb, PG_W, pWl1, tid);
    stage_A_g(smc, PG_A, h, row0, M, tid);
    asm volatile("cp.async.wait_group 0;");
    __syncthreads();

    float acc[8][4]; ZERO_ACC(acc);
    gemm_tile(sb, PG_A, PG_W, lid, wm, wn, acc);

    float hv[8][4];
    #pragma unroll
    for (int rr = 0; rr < 2; rr++) {
        int gr = row0 + wm*16 + rr*8 + (lid >> 2);
        bool rv = (gr < M);
        float invdeg = rv ? 1.0f / fmaxf(__ldg(deg + gr), 1.0f) : 1.0f;
        #pragma unroll
        for (int nj = 0; nj < 8; nj++) {
            int c = wn*64 + nj*8 + (lid & 3)*2;
            float2 ag = rv ? *(const float2*)(agg + (size_t)gr*128 + c) : make_float2(0.f,0.f);
            float o0 = fmaf(ag.x, invdeg, acc[nj][rr*2]);
            float o1 = fmaf(ag.y, invdeg, acc[nj][rr*2+1]);
            o0 = o0 >= 0.f ? o0 : SLOPE*o0;
            o1 = o1 >= 0.f ? o1 : SLOPE*o1;
            hv[nj][rr*2] = o0; hv[nj][rr*2+1] = o1;
            if (rv) *(float2*)(cur + (size_t)gr*128 + c) = make_float2(o0, o1);
        }
    }
    __syncthreads();

    stage_W(sb, PG_W, pWn2, tid);
    stage_A_r(smc, PG_A, hv, lid, wm, wn, -1);
    asm volatile("cp.async.wait_group 0;");
    __syncthreads();
    ZERO_ACC(acc);
    gemm_tile(sb, PG_A, PG_W, lid, wm, wn, acc);
    write_plain(HW, M, row0, lid, wm, wn, acc);
}

// ---------------- K3: FINNORM + time-gate + gated fusion + tdiff (+ next h@Wn1) ----------------
__global__ __launch_bounds__(NTHR, 1) void k3_kernel(
    const float* __restrict__ cur, const float* __restrict__ h,
    const unsigned char* __restrict__ pWl2, const unsigned char* __restrict__ pTg,
    const unsigned char* __restrict__ pGa,  const unsigned char* __restrict__ pGb,
    const unsigned char* __restrict__ pTd,  const unsigned char* __restrict__ pWn1,
    const float* __restrict__ tgb, const float* __restrict__ gateb,
    const float* __restrict__ tdb,
    const float* __restrict__ agg, const float* __restrict__ deg,
    float* __restrict__ hout, float* __restrict__ HWout, int M, int doHW)
{
    extern __shared__ char smc[];
    uint32_t sb = smem_u32(smc);
    int tid = threadIdx.x, wid = tid >> 5, lid = tid & 31;
    int wm = wid & 7, wn = wid >> 3;
    int row0 = blockIdx.x * 128;

    if (tid < 128) {
        ((float*)(smc + K3_BTG))[tid] = __ldg(tgb + tid);
        ((float*)(smc + K3_BGA))[tid] = __ldg(gateb + tid);
        ((float*)(smc + K3_BTD))[tid] = __ldg(tdb + tid);
    }
    stage_W(sb, K3_W, pWl2, tid);
    stage_A_g(smc, K3_A1, cur, row0, M, tid);
    stage_A_g(smc, K3_A2, h,   row0, M, tid);
    asm volatile("cp.async.wait_group 0;");
    __syncthreads();

    const float* btg = (const float*)(smc + K3_BTG);
    const float* bga = (const float*)(smc + K3_BGA);
    const float* btd = (const float*)(smc + K3_BTD);
    float* sred = (float*)(smc + K3_SRED);

    float acc[8][4], hv[8][4];

    // ---- phase 0: nrm = l2norm(leaky(agg/deg + cur@Wl2)) ----
    ZERO_ACC(acc);
    gemm_tile(sb, K3_A1, K3_W, lid, wm, wn, acc);
    #pragma unroll
    for (int rr = 0; rr < 2; rr++) {
        int row = wm*16 + rr*8 + (lid >> 2);
        int gr = row0 + row;
        bool rv = (gr < M);
        float invdeg = rv ? 1.0f / fmaxf(__ldg(deg + gr), 1.0f) : 1.0f;
        float ss = 0.0f;
        #pragma unroll
        for (int nj = 0; nj < 8; nj++) {
            int c = wn*64 + nj*8 + (lid & 3)*2;
            float2 ag = rv ? *(const float2*)(agg + (size_t)gr*128 + c) : make_float2(0.f,0.f);
            float o0 = fmaf(ag.x, invdeg, acc[nj][rr*2]);
            float o1 = fmaf(ag.y, invdeg, acc[nj][rr*2+1]);
            o0 = o0 >= 0.f ? o0 : SLOPE*o0;
            o1 = o1 >= 0.f ? o1 : SLOPE*o1;
            hv[nj][rr*2] = o0; hv[nj][rr*2+1] = o1;
            ss += o0*o0 + o1*o1;
        }
        ss += __shfl_xor_sync(0xffffffffu, ss, 1);
        ss += __shfl_xor_sync(0xffffffffu, ss, 2);
        if ((lid & 3) == 0) sred[wn*128 + row] = ss;
    }
    __syncthreads();
    #pragma unroll
    for (int rr = 0; rr < 2; rr++) {
        int row = wm*16 + rr*8 + (lid >> 2);
        float inv = 1.0f / fmaxf(sqrtf(sred[row] + sred[128 + row]), 1e-12f);
        #pragma unroll
        for (int nj = 0; nj < 8; nj++) { hv[nj][rr*2] *= inv; hv[nj][rr*2+1] *= inv; }
    }
    __syncthreads();

    // ---- phase 1: time gate ----
    stage_W(sb, K3_W, pTg, tid);
    stage_A_r(smc, K3_A1, hv, lid, wm, wn, -1);
    asm volatile("cp.async.wait_group 0;");
    __syncthreads();
    ZERO_ACC(acc);
    gemm_tile(sb, K3_A1, K3_W, lid, wm, wn, acc);
    #pragma unroll
    for (int rr = 0; rr < 2; rr++) {
        int row = wm*16 + rr*8 + (lid >> 2);
        #pragma unroll
        for (int nj = 0; nj < 8; nj++) {
            int c = wn*64 + nj*8 + (lid & 3)*2;
            float2 nv = readA2(smc, K3_A1, row, c);
            float2 hh = readA2(smc, K3_A2, row, c);
            float g0 = sigf(acc[nj][rr*2]   + btg[c]);
            float g1 = sigf(acc[nj][rr*2+1] + btg[c+1]);
            hv[nj][rr*2]   = g0*nv.x + (1.f-g0)*hh.x;
            hv[nj][rr*2+1] = g1*nv.y + (1.f-g1)*hh.y;
        }
    }
    __syncthreads();

    // ---- phase 2: gated fusion ----
    stage_W(sb, K3_W, pGa, tid);
    stage_A_r(smc, K3_A1, hv, lid, wm, wn, -1);
    asm volatile("cp.async.wait_group 0;");
    __syncthreads();
    ZERO_ACC(acc);
    gemm_tile(sb, K3_A1, K3_W, lid, wm, wn, acc);
    __syncthreads();
    stage_W(sb, K3_W, pGb, tid);
    asm volatile("cp.async.wait_group 0;");
    __syncthreads();
    gemm_tile(sb, K3_A2, K3_W, lid, wm, wn, acc);
    #pragma unroll
    for (int rr = 0; rr < 2; rr++) {
        int row = wm*16 + rr*8 + (lid >> 2);
        #pragma unroll
        for (int nj = 0; nj < 8; nj++) {
            int c = wn*64 + nj*8 + (lid & 3)*2;
            float2 hh = readA2(smc, K3_A2, row, c);
            float g0 = sigf(acc[nj][rr*2]   + bga[c]);
            float g1 = sigf(acc[nj][rr*2+1] + bga[c+1]);
            hv[nj][rr*2]   = g0*hv[nj][rr*2]   + (1.f-g0)*hh.x;
            hv[nj][rr*2+1] = g1*hv[nj][rr*2+1] + (1.f-g1)*hh.y;
        }
    }
    __syncthreads();

    // ---- phase 3: tdiff ----
    stage_W(sb, K3_W, pTd, tid);
    stage_A_r(smc, K3_A1, hv, lid, wm, wn, K3_A2);
    asm volatile("cp.async.wait_group 0;");
    __syncthreads();
    ZERO_ACC(acc);
    gemm_tile(sb, K3_A1, K3_W, lid, wm, wn, acc);
    #pragma unroll
    for (int rr = 0; rr < 2; rr++) {
        int gr = row0 + wm*16 + rr*8 + (lid >> 2);
        bool rv = (gr < M);
        #pragma unroll
        for (int nj = 0; nj < 8; nj++) {
            int c = wn*64 + nj*8 + (lid & 3)*2;
            float y0 = fmaxf(acc[nj][rr*2]   + btd[c],   0.f);
            float y1 = fmaxf(acc[nj][rr*2+1] + btd[c+1], 0.f);
            hv[nj][rr*2]   += y0;
            hv[nj][rr*2+1] += y1;
            if (rv) *(float2*)(hout + (size_t)gr*128 + c) =
                        make_float2(hv[nj][rr*2], hv[nj][rr*2+1]);
        }
    }

    // ---- phase 4 (optional): HW_next = h_next@Wn1 ----
    if (doHW) {
        __syncthreads();
        stage_W(sb, K3_W, pWn1, tid);
        stage_A_r(smc, K3_A1, hv, lid, wm, wn, -1);
        asm volatile("cp.async.wait_group 0;");
        __syncthreads();
        ZERO_ACC(acc);
        gemm_tile(sb, K3_A1, K3_W, lid, wm, wn, acc);
        write_plain(HWout, M, row0, lid, wm, wn, acc);
    }
}

// ---------------- host driver ----------------
extern "C" void kernel_launch(void* const* d_in, const int* in_sizes, int n_in,
                              void* d_out, int out_size) {
    const int*   src     = (const int*)d_in[0];
    const int*   dst     = (const int*)d_in[1];
    const int*   ety     = (const int*)d_in[2];
    const float* dyn     = (const float*)d_in[3];
    const float* emb_rel = (const float*)d_in[4];
    const float* Wn1     = (const float*)d_in[5];
    const float* Wl1     = (const float*)d_in[6];
    const float* Wn2     = (const float*)d_in[7];
    const float* Wl2     = (const float*)d_in[8];
    const float* gWx     = (const float*)d_in[9];
    const float* gWh     = (const float*)d_in[10];
    const float* gbx     = (const float*)d_in[11];
    const float* gbh     = (const float*)d_in[12];
    const float* gateW   = (const float*)d_in[13];
    const float* gateb   = (const float*)d_in[14];
    const float* tdW     = (const float*)d_in[15];
    const float* tdb     = (const float*)d_in[16];
    const float* tgW     = (const float*)d_in[17];
    const float* tgb     = (const float*)d_in[18];
    float* out = (float*)d_out;

    float *hA,*hB,*cur,*HW,*agg,*deg,*relA,*relB,*R1,*R2;
    unsigned char* Wp;
    cudaGetSymbolAddress((void**)&hA,  g_hA);
    cudaGetSymbolAddress((void**)&hB,  g_hB);
    cudaGetSymbolAddress((void**)&cur, g_cur);
    cudaGetSymbolAddress((void**)&HW,  g_HW);
    cudaGetSymbolAddress((void**)&agg, g_agg);
    cudaGetSymbolAddress((void**)&deg, g_deg);
    cudaGetSymbolAddress((void**)&relA,g_relA);
    cudaGetSymbolAddress((void**)&relB,g_relB);
    cudaGetSymbolAddress((void**)&R1,  g_R1);
    cudaGetSymbolAddress((void**)&R2,  g_R2);
    cudaGetSymbolAddress((void**)&Wp,  g_Wpack);

    cudaFuncSetAttribute((const void*)plain_gemm, cudaFuncAttributeMaxDynamicSharedMemorySize, PG_SIZE);
    cudaFuncSetAttribute((const void*)k2_kernel,  cudaFuncAttributeMaxDynamicSharedMemorySize, PG_SIZE);
    cudaFuncSetAttribute((const void*)k3_kernel,  cudaFuncAttributeMaxDynamicSharedMemorySize, K3_SIZE);
    cudaFuncSetAttribute((const void*)gru_mma,    cudaFuncAttributeMaxDynamicSharedMemorySize, K3_SIZE);

    const unsigned char* pWn1 = Wp + 0*65536;
    const unsigned char* pWl1 = Wp + 1*65536;
    const unsigned char* pWn2 = Wp + 2*65536;
    const unsigned char* pWl2 = Wp + 3*65536;
    const unsigned char* pTg  = Wp + 4*65536;
    const unsigned char* pGa  = Wp + 5*65536;
    const unsigned char* pGb  = Wp + 6*65536;
    const unsigned char* pTd  = Wp + 7*65536;

    const int GB = (NENT + 127) / 128;   // 782
    const int EB = (EE*32 + 255) / 256;

    pack_kernel<<<17, 256>>>(Wn1, Wl1, Wn2, Wl2, tgW, gateW, tdW, gWx, gWh);
    l2norm_kernel<<<(NENT + 7)/8, 256>>>(dyn, hA, NENT);
    plain_gemm<<<GB, NTHR, PG_SIZE>>>(hA, pWn1, HW, NENT);

    const float* relPrev = emb_rel;
    float* relBufs[2] = { relB, relA };
    float* h     = hA;
    float* hnext = hB;

    for (int t = 0; t < TT; t++) {
        const int* sT = src + t*EE;
        const int* dT = dst + t*EE;
        const int* eT = ety + t*EE;
        float* relNext = relBufs[t & 1];

        cudaMemsetAsync(agg, 0, (size_t)NENT*HDIM*sizeof(float));
        cudaMemsetAsync(deg, 0, (size_t)NENT*sizeof(float));

        gru_mma<<<4, NTHR, K3_SIZE>>>(emb_rel, relPrev, Wp, gbx, gbh, relNext, R1, R2);

        // layer 1
        edge_kernel<<<EB, 256>>>(sT, dT, eT, HW, R1, agg, deg, EE, 1);
        k2_kernel<<<GB, NTHR, PG_SIZE>>>(h, pWl1, pWn2, cur, HW, NENT, agg, deg);

        // layer 2
        cudaMemsetAsync(agg, 0, (size_t)NENT*HDIM*sizeof(float));
        edge_kernel<<<EB, 256>>>(sT, dT, eT, HW, R2, agg, deg, EE, 0);

        float* target = (t == TT-1) ? out : hnext;
        k3_kernel<<<GB, NTHR, K3_SIZE>>>(cur, h, pWl2, pTg, pGa, pGb, pTd, pWn1,
                                         tgb, gateb, tdb, agg, deg,
                                         target, HW, NENT, (t < TT-1) ? 1 : 0);

        relPrev = relNext;
        if (t < TT-1) { float* tmp = h; h = hnext; hnext = tmp; }
    }
}